// round 1
// baseline (speedup 1.0000x reference)
#include <cuda_runtime.h>
#include <math.h>

// Problem shapes (fixed per setup_inputs)
#define Bb 8
#define Nn 4096
#define Mm 2048
#define Dd 512

// ---------------- scratch (device globals: allocation-free) ----------------
__device__ float g_fn[(size_t)Bb * Nn * Dd];   // f1, then normalized in place (67 MB)
__device__ float g_tnT[(size_t)Dd * Mm];       // normalized text row-1, transposed [D][M] (4 MB)
__device__ float g_e[(size_t)Bb * Nn * Mm];    // exp(sim) (268 MB)
__device__ float g_s[Bb * Mm];                 // per-(b,m) column sums over N

// ---------------- K0: zero the column-sum accumulator ----------------
__global__ void k_zero_s() {
    int i = blockIdx.x * 256 + threadIdx.x;
    if (i < Bb * Mm) g_s[i] = 0.f;
}

// ---------------- K1: normalize text[1] -> g_tnT; broadcast t1 to out[...,512:] ----
// grid: Mm blocks, 128 threads (each thread owns 4 consecutive d via float4)
__global__ void k_text(const float* __restrict__ text, float* __restrict__ out) {
    int m = blockIdx.x;
    int tid = threadIdx.x;
    const float4* t1 = (const float4*)(text + (size_t)Mm * Dd + (size_t)m * Dd);
    float4 v = t1[tid];
    float ss = v.x * v.x + v.y * v.y + v.z * v.z + v.w * v.w;
#pragma unroll
    for (int o = 16; o > 0; o >>= 1) ss += __shfl_xor_sync(0xffffffffu, ss, o);
    __shared__ float ws[4];
    if ((tid & 31) == 0) ws[tid >> 5] = ss;
    __syncthreads();
    float tot = ws[0] + ws[1] + ws[2] + ws[3];
    float inv = 1.f / fmaxf(sqrtf(tot), 1e-8f);

    int d = tid * 4;
    g_tnT[(size_t)(d + 0) * Mm + m] = v.x * inv;
    g_tnT[(size_t)(d + 1) * Mm + m] = v.y * inv;
    g_tnT[(size_t)(d + 2) * Mm + m] = v.z * inv;
    g_tnT[(size_t)(d + 3) * Mm + m] = v.w * inv;

#pragma unroll
    for (int b = 0; b < Bb; b++) {
        float4* o = (float4*)(out + ((size_t)(b * Mm + m)) * (2 * Dd) + Dd);
        o[tid] = v;  // unnormalized t1, per reference concat
    }
}

// ---------------- K2a: f1 = features @ W + bias -> g_fn ----------------
// Classic 128x128x8 fp32 tiled GEMM, 256 threads, 8x8 micro-tile.
// grid: (Dd/128=4, (Bb*Nn)/128=256)
__global__ __launch_bounds__(256, 2)
void k_linear(const float* __restrict__ A, const float* __restrict__ W,
              const float* __restrict__ bias) {
    __shared__ float sm[2048];
    float* sA = sm;            // [8][128]  (k-major, transposed A tile)
    float* sB = sm + 1024;     // [8][128]

    int tid = threadIdx.x;
    int tx = tid & 15, ty = tid >> 4;
    int m0 = blockIdx.y * 128, n0 = blockIdx.x * 128;

    float acc[8][8];
#pragma unroll
    for (int i = 0; i < 8; i++)
#pragma unroll
        for (int j = 0; j < 8; j++) acc[i][j] = 0.f;

    int ar = tid >> 1, ak = (tid & 1) * 4;       // A tile: 128 rows x 8 k
    int br = tid >> 5, bc = (tid & 31) * 4;      // B tile: 8 k x 128 n
    const float* Ap = A + (size_t)(m0 + ar) * Dd + ak;
    const float* Bp = W + (size_t)br * Dd + n0 + bc;

    for (int k0 = 0; k0 < Dd; k0 += 8) {
        float4 av = *(const float4*)(Ap + k0);
        sA[(ak + 0) * 128 + ar] = av.x;
        sA[(ak + 1) * 128 + ar] = av.y;
        sA[(ak + 2) * 128 + ar] = av.z;
        sA[(ak + 3) * 128 + ar] = av.w;
        float4 bv = *(const float4*)(Bp + (size_t)k0 * Dd);
        *(float4*)(sB + br * 128 + bc) = bv;
        __syncthreads();
#pragma unroll
        for (int kk = 0; kk < 8; kk++) {
            float a[8], b2[8];
            *(float4*)(a)      = *(float4*)(sA + kk * 128 + ty * 8);
            *(float4*)(a + 4)  = *(float4*)(sA + kk * 128 + ty * 8 + 4);
            *(float4*)(b2)     = *(float4*)(sB + kk * 128 + tx * 8);
            *(float4*)(b2 + 4) = *(float4*)(sB + kk * 128 + tx * 8 + 4);
#pragma unroll
            for (int i = 0; i < 8; i++)
#pragma unroll
                for (int j = 0; j < 8; j++) acc[i][j] += a[i] * b2[j];
        }
        __syncthreads();
    }

    int row0 = m0 + ty * 8, col0 = n0 + tx * 8;
    float bs[8];
    *(float4*)(bs)     = *(const float4*)(bias + col0);
    *(float4*)(bs + 4) = *(const float4*)(bias + col0 + 4);
#pragma unroll
    for (int i = 0; i < 8; i++) {
        float4 o1 = make_float4(acc[i][0] + bs[0], acc[i][1] + bs[1],
                                acc[i][2] + bs[2], acc[i][3] + bs[3]);
        float4 o2 = make_float4(acc[i][4] + bs[4], acc[i][5] + bs[5],
                                acc[i][6] + bs[6], acc[i][7] + bs[7]);
        float* dst = g_fn + (size_t)(row0 + i) * Dd + col0;
        *(float4*)(dst)     = o1;
        *(float4*)(dst + 4) = o2;
    }
}

// ---------------- K2b: row-normalize g_fn in place ----------------
// grid: Bb*Nn blocks, 128 threads
__global__ void k_normrows() {
    int r = blockIdx.x;
    int tid = threadIdx.x;
    float4* row = (float4*)(g_fn + (size_t)r * Dd);
    float4 v = row[tid];
    float ss = v.x * v.x + v.y * v.y + v.z * v.z + v.w * v.w;
#pragma unroll
    for (int o = 16; o > 0; o >>= 1) ss += __shfl_xor_sync(0xffffffffu, ss, o);
    __shared__ float ws[4];
    if ((tid & 31) == 0) ws[tid >> 5] = ss;
    __syncthreads();
    float tot = ws[0] + ws[1] + ws[2] + ws[3];
    float inv = 1.f / fmaxf(sqrtf(tot), 1e-8f);
    v.x *= inv; v.y *= inv; v.z *= inv; v.w *= inv;
    row[tid] = v;
}

// ---------------- K3: e = exp(fn @ tn^T) -> g_e ; column sums -> g_s -------
// grid: (Mm/128=16, Nn/128=32, Bb)
__global__ __launch_bounds__(256, 2)
void k_sim() {
    __shared__ float sm[2048];
    float* sA = sm;
    float* sB = sm + 1024;

    int b = blockIdx.z;
    int tid = threadIdx.x;
    int tx = tid & 15, ty = tid >> 4;
    int n0 = blockIdx.y * 128;  // rows (over N)
    int c0 = blockIdx.x * 128;  // cols (over M)

    float acc[8][8];
#pragma unroll
    for (int i = 0; i < 8; i++)
#pragma unroll
        for (int j = 0; j < 8; j++) acc[i][j] = 0.f;

    int ar = tid >> 1, ak = (tid & 1) * 4;
    int br = tid >> 5, bc = (tid & 31) * 4;
    const float* Ap = g_fn + ((size_t)b * Nn + n0 + ar) * Dd + ak;
    const float* Bp = g_tnT + (size_t)br * Mm + c0 + bc;

    for (int k0 = 0; k0 < Dd; k0 += 8) {
        float4 av = *(const float4*)(Ap + k0);
        sA[(ak + 0) * 128 + ar] = av.x;
        sA[(ak + 1) * 128 + ar] = av.y;
        sA[(ak + 2) * 128 + ar] = av.z;
        sA[(ak + 3) * 128 + ar] = av.w;
        float4 bv = *(const float4*)(Bp + (size_t)k0 * Mm);
        *(float4*)(sB + br * 128 + bc) = bv;
        __syncthreads();
#pragma unroll
        for (int kk = 0; kk < 8; kk++) {
            float a[8], b2[8];
            *(float4*)(a)      = *(float4*)(sA + kk * 128 + ty * 8);
            *(float4*)(a + 4)  = *(float4*)(sA + kk * 128 + ty * 8 + 4);
            *(float4*)(b2)     = *(float4*)(sB + kk * 128 + tx * 8);
            *(float4*)(b2 + 4) = *(float4*)(sB + kk * 128 + tx * 8 + 4);
#pragma unroll
            for (int i = 0; i < 8; i++)
#pragma unroll
                for (int j = 0; j < 8; j++) acc[i][j] += a[i] * b2[j];
        }
        __syncthreads();
    }

    // epilogue: exp, store e, reduce column sums
    int row0 = n0 + ty * 8, col0 = c0 + tx * 8;
    float csum[8];
#pragma unroll
    for (int j = 0; j < 8; j++) csum[j] = 0.f;
#pragma unroll
    for (int i = 0; i < 8; i++) {
#pragma unroll
        for (int j = 0; j < 8; j++) {
            float e = expf(acc[i][j]);
            acc[i][j] = e;
            csum[j] += e;
        }
        float* dst = g_e + ((size_t)b * Nn + row0 + i) * Mm + col0;
        *(float4*)(dst)     = make_float4(acc[i][0], acc[i][1], acc[i][2], acc[i][3]);
        *(float4*)(dst + 4) = make_float4(acc[i][4], acc[i][5], acc[i][6], acc[i][7]);
    }
    // smem tree: red[ty][col], 16x128
    *(float4*)(sm + ty * 128 + tx * 8)     = make_float4(csum[0], csum[1], csum[2], csum[3]);
    *(float4*)(sm + ty * 128 + tx * 8 + 4) = make_float4(csum[4], csum[5], csum[6], csum[7]);
    __syncthreads();
    if (tid < 128) {
        float t = 0.f;
#pragma unroll
        for (int y = 0; y < 16; y++) t += sm[y * 128 + tid];
        atomicAdd(&g_s[b * Mm + c0 + tid], t);
    }
}

// ---------------- K4: out[...,:512] = (e^T @ features) / s ----------------
// grid: (Dd/128=4, Mm/128=16, Bb)
__global__ __launch_bounds__(256, 2)
void k_out(const float* __restrict__ feat, float* __restrict__ out) {
    __shared__ float sm[2048];
    float* sA = sm;
    float* sB = sm + 1024;

    int b = blockIdx.z;
    int tid = threadIdx.x;
    int tx = tid & 15, ty = tid >> 4;
    int m0 = blockIdx.y * 128;  // rows (over M)
    int d0 = blockIdx.x * 128;  // cols (over D)

    float acc[8][8];
#pragma unroll
    for (int i = 0; i < 8; i++)
#pragma unroll
        for (int j = 0; j < 8; j++) acc[i][j] = 0.f;

    // A[m][k=n] = e[b][n][m] -> tile is 8 contiguous rows of g_e
    int ar = tid >> 5, ac = (tid & 31) * 4;
    const float* Ap = g_e + ((size_t)b * Nn + ar) * Mm + m0 + ac;
    const float* Bp = feat + ((size_t)b * Nn + ar) * Dd + d0 + ac;

    for (int k0 = 0; k0 < Nn; k0 += 8) {
        float4 av = *(const float4*)(Ap + (size_t)k0 * Mm);
        *(float4*)(sA + ar * 128 + ac) = av;
        float4 bv = *(const float4*)(Bp + (size_t)k0 * Dd);
        *(float4*)(sB + ar * 128 + ac) = bv;
        __syncthreads();
#pragma unroll
        for (int kk = 0; kk < 8; kk++) {
            float a[8], b2[8];
            *(float4*)(a)      = *(float4*)(sA + kk * 128 + ty * 8);
            *(float4*)(a + 4)  = *(float4*)(sA + kk * 128 + ty * 8 + 4);
            *(float4*)(b2)     = *(float4*)(sB + kk * 128 + tx * 8);
            *(float4*)(b2 + 4) = *(float4*)(sB + kk * 128 + tx * 8 + 4);
#pragma unroll
            for (int i = 0; i < 8; i++)
#pragma unroll
                for (int j = 0; j < 8; j++) acc[i][j] += a[i] * b2[j];
        }
        __syncthreads();
    }

    int row0 = m0 + ty * 8, col0 = d0 + tx * 8;
#pragma unroll
    for (int i = 0; i < 8; i++) {
        float inv = 1.f / g_s[b * Mm + row0 + i];
        float4 o1 = make_float4(acc[i][0] * inv, acc[i][1] * inv,
                                acc[i][2] * inv, acc[i][3] * inv);
        float4 o2 = make_float4(acc[i][4] * inv, acc[i][5] * inv,
                                acc[i][6] * inv, acc[i][7] * inv);
        float* dst = out + ((size_t)(b * Mm + row0 + i)) * (2 * Dd) + col0;
        *(float4*)(dst)     = o1;
        *(float4*)(dst + 4) = o2;
    }
}

// ---------------- launch ----------------
extern "C" void kernel_launch(void* const* d_in, const int* in_sizes, int n_in,
                              void* d_out, int out_size) {
    const float* features = (const float*)d_in[0];  // [8,4096,512]
    const float* text     = (const float*)d_in[1];  // [2,2048,512]
    const float* W        = (const float*)d_in[2];  // [512,512]
    const float* bias     = (const float*)d_in[3];  // [512]
    float* out = (float*)d_out;                     // [8,2048,1024]

    k_zero_s<<<(Bb * Mm + 255) / 256, 256>>>();
    k_text<<<Mm, 128>>>(text, out);
    k_linear<<<dim3(Dd / 128, (Bb * Nn) / 128), 256>>>(features, W, bias);
    k_normrows<<<Bb * Nn, 128>>>();
    k_sim<<<dim3(Mm / 128, Nn / 128, Bb), 256>>>();
    k_out<<<dim3(Dd / 128, Mm / 128, Bb), 256>>>(features, out);
}

// round 2
// speedup vs baseline: 2.8248x; 2.8248x over previous
#include <cuda_runtime.h>
#include <math.h>

#define Bb 8
#define Nn 4096
#define Mm 2048
#define Dd 512
#define SST 136   // smem row stride (words): bank = (8k+m)%32, conflict-free frags

// ---------------- scratch ----------------
__device__ float g_fn[(size_t)Bb * Nn * Dd];   // f1 then normalized (67 MB)
__device__ float g_tnT[(size_t)Dd * Mm];       // normalized text row-1, [D][M]
__device__ float g_e[(size_t)Bb * Nn * Mm];    // exp(sim) (268 MB)
__device__ float g_s[Bb * Mm];                 // column sums over N

__device__ __forceinline__ unsigned f2tf(float x) {
    unsigned u; asm("cvt.rna.tf32.f32 %0, %1;" : "=r"(u) : "f"(x)); return u;
}

__device__ __forceinline__ void mma_tf32(float& d0, float& d1, float& d2, float& d3,
                                         unsigned a0, unsigned a1, unsigned a2, unsigned a3,
                                         unsigned b0, unsigned b1) {
    asm volatile(
        "mma.sync.aligned.m16n8k8.row.col.f32.tf32.tf32.f32 "
        "{%0,%1,%2,%3}, {%4,%5,%6,%7}, {%8,%9}, {%0,%1,%2,%3};"
        : "+f"(d0), "+f"(d1), "+f"(d2), "+f"(d3)
        : "r"(a0), "r"(a1), "r"(a2), "r"(a3), "r"(b0), "r"(b1));
}

// ---------------- K0: zero g_s ----------------
__global__ void k_zero_s() {
    int i = blockIdx.x * 256 + threadIdx.x;
    if (i < Bb * Mm) g_s[i] = 0.f;
}

// ---------------- K1: text[1] -> normalized g_tnT; raw t1 -> out[...,512:] ----
__global__ void k_text(const float* __restrict__ text, float* __restrict__ out) {
    int m = blockIdx.x, tid = threadIdx.x;
    const float4* t1 = (const float4*)(text + (size_t)Mm * Dd + (size_t)m * Dd);
    float4 v = t1[tid];
    float ss = v.x * v.x + v.y * v.y + v.z * v.z + v.w * v.w;
#pragma unroll
    for (int o = 16; o > 0; o >>= 1) ss += __shfl_xor_sync(0xffffffffu, ss, o);
    __shared__ float ws[4];
    if ((tid & 31) == 0) ws[tid >> 5] = ss;
    __syncthreads();
    float inv = 1.f / fmaxf(sqrtf(ws[0] + ws[1] + ws[2] + ws[3]), 1e-8f);
    int d = tid * 4;
    g_tnT[(size_t)(d + 0) * Mm + m] = v.x * inv;
    g_tnT[(size_t)(d + 1) * Mm + m] = v.y * inv;
    g_tnT[(size_t)(d + 2) * Mm + m] = v.z * inv;
    g_tnT[(size_t)(d + 3) * Mm + m] = v.w * inv;
#pragma unroll
    for (int b = 0; b < Bb; b++) {
        float4* o = (float4*)(out + ((size_t)(b * Mm + m)) * (2 * Dd) + Dd);
        o[tid] = v;
    }
}

// ================= tf32 GEMM bodies =================
// Block 128x128, K-step 16, 256 thr = 8 warps (2x4), warp tile 64x32.
// sA/sB stored tf32 (unsigned), [k][SST] layout.

#define GEMM_DECLS                                                         \
    int tid = threadIdx.x, lane = tid & 31, warp = tid >> 5;               \
    int wm = warp >> 2, wn = warp & 3;                                     \
    int lg = lane >> 2, lt = lane & 3;                                     \
    float acc[4][4][4];                                                    \
    _Pragma("unroll") for (int i = 0; i < 4; i++)                          \
    _Pragma("unroll") for (int j = 0; j < 4; j++)                          \
    _Pragma("unroll") for (int r = 0; r < 4; r++) acc[i][j][r] = 0.f;

// transpose-fill A (row-major source, lda) into sA[k][SST]
#define LOAD_A_T(k0)                                                       \
    _Pragma("unroll") for (int i = 0; i < 2; i++) {                        \
        int f = tid * 2 + i;                                               \
        ra[i] = *(const float4*)(Abase + (size_t)(f >> 2) * lda + (k0) + (f & 3) * 4); }
#define STORE_A_T                                                          \
    _Pragma("unroll") for (int i = 0; i < 2; i++) {                        \
        int f = tid * 2 + i; int row = f >> 2, kc = (f & 3) * 4;           \
        sA[(kc + 0) * SST + row] = f2tf(ra[i].x);                          \
        sA[(kc + 1) * SST + row] = f2tf(ra[i].y);                          \
        sA[(kc + 2) * SST + row] = f2tf(ra[i].z);                          \
        sA[(kc + 3) * SST + row] = f2tf(ra[i].w); }

// direct-fill (k-major source, ld) into s[k][SST]
#define LOAD_KMAJ(dst, base, ld, k0)                                       \
    _Pragma("unroll") for (int i = 0; i < 2; i++) {                        \
        int f = tid * 2 + i;                                               \
        dst[i] = *(const float4*)((base) + (size_t)((k0) + (f >> 5)) * (ld) + (f & 31) * 4); }
#define STORE_KMAJ(sm, rg)                                                 \
    _Pragma("unroll") for (int i = 0; i < 2; i++) {                        \
        int f = tid * 2 + i; int bk = f >> 5, bn = (f & 31) * 4;           \
        sm[bk * SST + bn + 0] = f2tf(rg[i].x);                             \
        sm[bk * SST + bn + 1] = f2tf(rg[i].y);                             \
        sm[bk * SST + bn + 2] = f2tf(rg[i].z);                             \
        sm[bk * SST + bn + 3] = f2tf(rg[i].w); }

#define COMPUTE_K16                                                        \
    _Pragma("unroll") for (int kk = 0; kk < 2; kk++) {                     \
        int kb = kk * 8;                                                   \
        unsigned bf[4][2];                                                 \
        _Pragma("unroll") for (int nt = 0; nt < 4; nt++) {                 \
            int nb = wn * 32 + nt * 8 + lg;                                \
            bf[nt][0] = sB[(kb + lt) * SST + nb];                          \
            bf[nt][1] = sB[(kb + 4 + lt) * SST + nb]; }                    \
        _Pragma("unroll") for (int mt = 0; mt < 4; mt++) {                 \
            int mb = wm * 64 + mt * 16 + lg;                               \
            unsigned a0 = sA[(kb + lt) * SST + mb];                        \
            unsigned a1 = sA[(kb + lt) * SST + mb + 8];                    \
            unsigned a2 = sA[(kb + 4 + lt) * SST + mb];                    \
            unsigned a3 = sA[(kb + 4 + lt) * SST + mb + 8];                \
            _Pragma("unroll") for (int nt = 0; nt < 4; nt++)               \
                mma_tf32(acc[mt][nt][0], acc[mt][nt][1],                   \
                         acc[mt][nt][2], acc[mt][nt][3],                   \
                         a0, a1, a2, a3, bf[nt][0], bf[nt][1]); } }

// ---------------- K2a: f1 = features @ W + b -> g_fn ----------------
__global__ __launch_bounds__(256, 2)
void k_linear(const float* __restrict__ A, const float* __restrict__ W,
              const float* __restrict__ bias) {
    __shared__ unsigned sA[16 * SST];
    __shared__ unsigned sB[16 * SST];
    GEMM_DECLS
    int m0 = blockIdx.y * 128, n0 = blockIdx.x * 128;
    const float* Abase = A + (size_t)m0 * Dd;
    const int lda = Dd;
    const float* Bbase = W + n0;
    float4 ra[2], rb[2];
    LOAD_A_T(0) LOAD_KMAJ(rb, Bbase, Dd, 0)
    for (int k0 = 0; k0 < Dd; k0 += 16) {
        STORE_A_T STORE_KMAJ(sB, rb)
        __syncthreads();
        if (k0 + 16 < Dd) { LOAD_A_T(k0 + 16) LOAD_KMAJ(rb, Bbase, Dd, k0 + 16) }
        COMPUTE_K16
        __syncthreads();
    }
#pragma unroll
    for (int mt = 0; mt < 4; mt++) {
        int row = m0 + wm * 64 + mt * 16 + lg;
#pragma unroll
        for (int nt = 0; nt < 4; nt++) {
            int col = n0 + wn * 32 + nt * 8 + lt * 2;
            float b0 = bias[col], b1 = bias[col + 1];
            *(float2*)(g_fn + (size_t)row * Dd + col) =
                make_float2(acc[mt][nt][0] + b0, acc[mt][nt][1] + b1);
            *(float2*)(g_fn + (size_t)(row + 8) * Dd + col) =
                make_float2(acc[mt][nt][2] + b0, acc[mt][nt][3] + b1);
        }
    }
}

// ---------------- K2b: row-normalize g_fn in place ----------------
__global__ void k_normrows() {
    int r = blockIdx.x, tid = threadIdx.x;
    float4* row = (float4*)(g_fn + (size_t)r * Dd);
    float4 v = row[tid];
    float ss = v.x * v.x + v.y * v.y + v.z * v.z + v.w * v.w;
#pragma unroll
    for (int o = 16; o > 0; o >>= 1) ss += __shfl_xor_sync(0xffffffffu, ss, o);
    __shared__ float ws[4];
    if ((tid & 31) == 0) ws[tid >> 5] = ss;
    __syncthreads();
    float inv = 1.f / fmaxf(sqrtf(ws[0] + ws[1] + ws[2] + ws[3]), 1e-8f);
    v.x *= inv; v.y *= inv; v.z *= inv; v.w *= inv;
    row[tid] = v;
}

// ---------------- K3: e = exp(fn @ tnT) -> g_e; col sums -> g_s ----------
__global__ __launch_bounds__(256, 2)
void k_sim() {
    __shared__ unsigned sA[16 * SST];
    __shared__ unsigned sB[16 * SST];
    GEMM_DECLS
    int b = blockIdx.z;
    int n0 = blockIdx.y * 128;  // GEMM-M (over N)
    int c0 = blockIdx.x * 128;  // GEMM-N (over M)
    const float* Abase = g_fn + ((size_t)b * Nn + n0) * Dd;
    const int lda = Dd;
    const float* Bbase = g_tnT + c0;
    float4 ra[2], rb[2];
    LOAD_A_T(0) LOAD_KMAJ(rb, Bbase, Mm, 0)
    for (int k0 = 0; k0 < Dd; k0 += 16) {
        STORE_A_T STORE_KMAJ(sB, rb)
        __syncthreads();
        if (k0 + 16 < Dd) { LOAD_A_T(k0 + 16) LOAD_KMAJ(rb, Bbase, Mm, k0 + 16) }
        COMPUTE_K16
        __syncthreads();
    }
    // epilogue: exp, store e, fused column sums
    float cs[4][2];
#pragma unroll
    for (int nt = 0; nt < 4; nt++) { cs[nt][0] = 0.f; cs[nt][1] = 0.f; }
#pragma unroll
    for (int mt = 0; mt < 4; mt++) {
        int row = n0 + wm * 64 + mt * 16 + lg;
#pragma unroll
        for (int nt = 0; nt < 4; nt++) {
            int col = c0 + wn * 32 + nt * 8 + lt * 2;
            float e0 = __expf(acc[mt][nt][0]);
            float e1 = __expf(acc[mt][nt][1]);
            float e2 = __expf(acc[mt][nt][2]);
            float e3 = __expf(acc[mt][nt][3]);
            *(float2*)(g_e + ((size_t)b * Nn + row) * Mm + col) = make_float2(e0, e1);
            *(float2*)(g_e + ((size_t)b * Nn + row + 8) * Mm + col) = make_float2(e2, e3);
            cs[nt][0] += e0 + e2;
            cs[nt][1] += e1 + e3;
        }
    }
    // reduce over groupID lanes (offsets 4,8,16), then lanes 0-3 atomicAdd
#pragma unroll
    for (int nt = 0; nt < 4; nt++)
#pragma unroll
        for (int p = 0; p < 2; p++) {
            float v = cs[nt][p];
            v += __shfl_xor_sync(0xffffffffu, v, 4);
            v += __shfl_xor_sync(0xffffffffu, v, 8);
            v += __shfl_xor_sync(0xffffffffu, v, 16);
            if (lg == 0)
                atomicAdd(&g_s[b * Mm + c0 + wn * 32 + nt * 8 + lt * 2 + p], v);
        }
}

// ---------------- K4: out[...,:512] = (e^T @ features) / s ----------------
__global__ __launch_bounds__(256, 2)
void k_out(const float* __restrict__ feat, float* __restrict__ out) {
    __shared__ unsigned sA[16 * SST];
    __shared__ unsigned sB[16 * SST];
    GEMM_DECLS
    int b = blockIdx.z;
    int m0 = blockIdx.y * 128;  // GEMM-M (over M)
    int d0 = blockIdx.x * 128;  // GEMM-N (over D)
    // A[m][k=n] = g_e[b][n][m]: k-major rows of g_e
    const float* Abase = g_e + (size_t)b * Nn * Mm + m0;
    const float* Bbase = feat + (size_t)b * Nn * Dd + d0;
    float4 ra[2], rb[2];
    LOAD_KMAJ(ra, Abase, Mm, 0) LOAD_KMAJ(rb, Bbase, Dd, 0)
    for (int k0 = 0; k0 < Nn; k0 += 16) {
        STORE_KMAJ(sA, ra) STORE_KMAJ(sB, rb)
        __syncthreads();
        if (k0 + 16 < Nn) { LOAD_KMAJ(ra, Abase, Mm, k0 + 16) LOAD_KMAJ(rb, Bbase, Dd, k0 + 16) }
        COMPUTE_K16
        __syncthreads();
    }
#pragma unroll
    for (int mt = 0; mt < 4; mt++) {
        int row = m0 + wm * 64 + mt * 16 + lg;
        float i0 = 1.f / g_s[b * Mm + row];
        float i1 = 1.f / g_s[b * Mm + row + 8];
#pragma unroll
        for (int nt = 0; nt < 4; nt++) {
            int col = d0 + wn * 32 + nt * 8 + lt * 2;
            *(float2*)(out + ((size_t)(b * Mm + row)) * (2 * Dd) + col) =
                make_float2(acc[mt][nt][0] * i0, acc[mt][nt][1] * i0);
            *(float2*)(out + ((size_t)(b * Mm + row + 8)) * (2 * Dd) + col) =
                make_float2(acc[mt][nt][2] * i1, acc[mt][nt][3] * i1);
        }
    }
}

// ---------------- launch ----------------
extern "C" void kernel_launch(void* const* d_in, const int* in_sizes, int n_in,
                              void* d_out, int out_size) {
    const float* features = (const float*)d_in[0];
    const float* text     = (const float*)d_in[1];
    const float* W        = (const float*)d_in[2];
    const float* bias     = (const float*)d_in[3];
    float* out = (float*)d_out;

    k_zero_s<<<(Bb * Mm + 255) / 256, 256>>>();
    k_text<<<Mm, 128>>>(text, out);
    k_linear<<<dim3(Dd / 128, (Bb * Nn) / 128), 256>>>(features, W, bias);
    k_normrows<<<Bb * Nn, 128>>>();
    k_sim<<<dim3(Mm / 128, Nn / 128, Bb), 256>>>();
    k_out<<<dim3(Dd / 128, Mm / 128, Bb), 256>>>(features, out);
}

// round 3
// speedup vs baseline: 3.3319x; 1.1795x over previous
#include <cuda_runtime.h>
#include <cuda_bf16.h>
#include <math.h>

#define Bb 8
#define Nn 4096
#define Mm 2048
#define Dd 512
#define SST 136   // smem word stride; SST%32==8 -> fragment LDS conflict-free
typedef unsigned u32;

// ---------------- scratch ----------------
__device__ float g_fn[(size_t)Bb * Nn * Dd];   // f1 then normalized
__device__ float g_tnT[(size_t)Dd * Mm];       // normalized text row-1, [D][M]
__device__ float g_e[(size_t)Bb * Nn * Mm];    // exp(sim)
__device__ float g_s[Bb * Mm];                 // column sums over N

__device__ __forceinline__ u32 pk2(float lo, float hi) {
    __nv_bfloat162 h = __floats2bfloat162_rn(lo, hi);  // .x=lo(low half),.y=hi
    return *(u32*)&h;
}

__device__ __forceinline__ void mma_bf16(float& d0, float& d1, float& d2, float& d3,
                                         u32 a0, u32 a1, u32 a2, u32 a3,
                                         u32 b0, u32 b1) {
    asm volatile(
        "mma.sync.aligned.m16n8k16.row.col.f32.bf16.bf16.f32 "
        "{%0,%1,%2,%3}, {%4,%5,%6,%7}, {%8,%9}, {%0,%1,%2,%3};"
        : "+f"(d0), "+f"(d1), "+f"(d2), "+f"(d3)
        : "r"(a0), "r"(a1), "r"(a2), "r"(a3), "r"(b0), "r"(b1));
}

// ---------------- K0 / K1 / norm helpers ----------------
__global__ void k_zero_s() {
    int i = blockIdx.x * 256 + threadIdx.x;
    if (i < Bb * Mm) g_s[i] = 0.f;
}

__global__ void k_text(const float* __restrict__ text, float* __restrict__ out) {
    int m = blockIdx.x, tid = threadIdx.x;
    const float4* t1 = (const float4*)(text + (size_t)Mm * Dd + (size_t)m * Dd);
    float4 v = t1[tid];
    float ss = v.x * v.x + v.y * v.y + v.z * v.z + v.w * v.w;
#pragma unroll
    for (int o = 16; o > 0; o >>= 1) ss += __shfl_xor_sync(0xffffffffu, ss, o);
    __shared__ float ws[4];
    if ((tid & 31) == 0) ws[tid >> 5] = ss;
    __syncthreads();
    float inv = 1.f / fmaxf(sqrtf(ws[0] + ws[1] + ws[2] + ws[3]), 1e-8f);
    int d = tid * 4;
    g_tnT[(size_t)(d + 0) * Mm + m] = v.x * inv;
    g_tnT[(size_t)(d + 1) * Mm + m] = v.y * inv;
    g_tnT[(size_t)(d + 2) * Mm + m] = v.z * inv;
    g_tnT[(size_t)(d + 3) * Mm + m] = v.w * inv;
#pragma unroll
    for (int b = 0; b < Bb; b++) {
        float4* o = (float4*)(out + ((size_t)(b * Mm + m)) * (2 * Dd) + Dd);
        o[tid] = v;
    }
}

__global__ void k_normrows() {
    int r = blockIdx.x, tid = threadIdx.x;
    float4* row = (float4*)(g_fn + (size_t)r * Dd);
    float4 v = row[tid];
    float ss = v.x * v.x + v.y * v.y + v.z * v.z + v.w * v.w;
#pragma unroll
    for (int o = 16; o > 0; o >>= 1) ss += __shfl_xor_sync(0xffffffffu, ss, o);
    __shared__ float ws[4];
    if ((tid & 31) == 0) ws[tid >> 5] = ss;
    __syncthreads();
    float inv = 1.f / fmaxf(sqrtf(ws[0] + ws[1] + ws[2] + ws[3]), 1e-8f);
    v.x *= inv; v.y *= inv; v.z *= inv; v.w *= inv;
    row[tid] = v;
}

// ================= bf16 GEMM framework =================
// Block 128x128, k-step 16, 256 thr = 8 warps (2x4), warp tile 64x32.
// smem: packed bf16x2 words, layout [kw(0..7)][SST], double-buffered.

#define GEMM_DECLS                                                         \
    int tid = threadIdx.x, lane = tid & 31, warp = tid >> 5;               \
    int wm = warp >> 2, wn = warp & 3;                                     \
    int lg = lane >> 2, lt = lane & 3;                                     \
    float acc[4][4][4];                                                    \
    _Pragma("unroll") for (int i = 0; i < 4; i++)                          \
    _Pragma("unroll") for (int j = 0; j < 4; j++)                          \
    _Pragma("unroll") for (int r = 0; r < 4; r++) acc[i][j][r] = 0.f;

// A row-major source ([m][k], k contiguous): 2 float4 per thread
#define LOAD_ROWMAJ(k0)                                                    \
    _Pragma("unroll") for (int i = 0; i < 2; i++) {                        \
        int f = tid * 2 + i;                                               \
        ra[i] = *(const float4*)(Abase + (size_t)(f >> 2) * lda + (k0) + (f & 3) * 4); }
#define STORE_ROWMAJ(sm)                                                   \
    _Pragma("unroll") for (int i = 0; i < 2; i++) {                        \
        int f = tid * 2 + i; int row = f >> 2, kw = (f & 3) * 2;           \
        sm[kw * SST + row]       = pk2(ra[i].x, ra[i].y);                  \
        sm[(kw + 1) * SST + row] = pk2(ra[i].z, ra[i].w); }

// k-major source ([k][n], n contiguous): load rows 2kw, 2kw+1 and interleave
#define LOAD_KMAJ(lo, hi, base, ld, k0)                                    \
    { int kw = tid >> 5, c4 = (tid & 31) * 4;                              \
      lo = *(const float4*)((base) + (size_t)((k0) + 2 * kw) * (ld) + c4); \
      hi = *(const float4*)((base) + (size_t)((k0) + 2 * kw + 1) * (ld) + c4); }
#define STORE_KMAJ(sm, lo, hi)                                             \
    { int kw = tid >> 5, c4 = (tid & 31) * 4;                              \
      *(uint4*)(sm + kw * SST + c4) = make_uint4(                          \
          pk2(lo.x, hi.x), pk2(lo.y, hi.y), pk2(lo.z, hi.z), pk2(lo.w, hi.w)); }

#define COMPUTE16(sAp, sBp)                                                \
    { u32 bf[4][2];                                                        \
      _Pragma("unroll") for (int nt = 0; nt < 4; nt++) {                   \
          int nb = wn * 32 + nt * 8 + lg;                                  \
          bf[nt][0] = sBp[lt * SST + nb];                                  \
          bf[nt][1] = sBp[(lt + 4) * SST + nb]; }                          \
      _Pragma("unroll") for (int mt = 0; mt < 4; mt++) {                   \
          int mb = wm * 64 + mt * 16 + lg;                                 \
          u32 a0 = sAp[lt * SST + mb];                                     \
          u32 a1 = sAp[lt * SST + mb + 8];                                 \
          u32 a2 = sAp[(lt + 4) * SST + mb];                               \
          u32 a3 = sAp[(lt + 4) * SST + mb + 8];                           \
          _Pragma("unroll") for (int nt = 0; nt < 4; nt++)                 \
              mma_bf16(acc[mt][nt][0], acc[mt][nt][1],                     \
                       acc[mt][nt][2], acc[mt][nt][3],                     \
                       a0, a1, a2, a3, bf[nt][0], bf[nt][1]); } }

// ---------------- K2a: f1 = features @ W + b -> g_fn ----------------
__global__ __launch_bounds__(256, 2)
void k_linear(const float* __restrict__ A, const float* __restrict__ W,
              const float* __restrict__ bias) {
    __shared__ u32 sA[2][8 * SST], sB[2][8 * SST];
    GEMM_DECLS
    int m0 = blockIdx.y * 128, n0 = blockIdx.x * 128;
    const float* Abase = A + (size_t)m0 * Dd;
    const int lda = Dd;
    const float* Bbase = W + n0;
    float4 ra[2], blo, bhi;
    LOAD_ROWMAJ(0) LOAD_KMAJ(blo, bhi, Bbase, Dd, 0)
    STORE_ROWMAJ(sA[0]) STORE_KMAJ(sB[0], blo, bhi)
    int p = 0;
    for (int k0 = 0; k0 < Dd; k0 += 16) {
        bool nxt = (k0 + 16 < Dd);
        if (nxt) { LOAD_ROWMAJ(k0 + 16) LOAD_KMAJ(blo, bhi, Bbase, Dd, k0 + 16) }
        __syncthreads();
        COMPUTE16(sA[p], sB[p])
        if (nxt) { STORE_ROWMAJ(sA[p ^ 1]) STORE_KMAJ(sB[p ^ 1], blo, bhi) }
        p ^= 1;
    }
#pragma unroll
    for (int mt = 0; mt < 4; mt++) {
        int row = m0 + wm * 64 + mt * 16 + lg;
#pragma unroll
        for (int nt = 0; nt < 4; nt++) {
            int col = n0 + wn * 32 + nt * 8 + lt * 2;
            float b0 = bias[col], b1 = bias[col + 1];
            *(float2*)(g_fn + (size_t)row * Dd + col) =
                make_float2(acc[mt][nt][0] + b0, acc[mt][nt][1] + b1);
            *(float2*)(g_fn + (size_t)(row + 8) * Dd + col) =
                make_float2(acc[mt][nt][2] + b0, acc[mt][nt][3] + b1);
        }
    }
}

// ---------------- K3: e = exp(fn @ tnT) -> g_e; col sums -> g_s ----------
__global__ __launch_bounds__(256, 2)
void k_sim() {
    __shared__ u32 sA[2][8 * SST], sB[2][8 * SST];
    GEMM_DECLS
    int b = blockIdx.z;
    int n0 = blockIdx.y * 128;  // GEMM-M (over N)
    int c0 = blockIdx.x * 128;  // GEMM-N (over M)
    const float* Abase = g_fn + ((size_t)b * Nn + n0) * Dd;
    const int lda = Dd;
    const float* Bbase = g_tnT + c0;
    float4 ra[2], blo, bhi;
    LOAD_ROWMAJ(0) LOAD_KMAJ(blo, bhi, Bbase, Mm, 0)
    STORE_ROWMAJ(sA[0]) STORE_KMAJ(sB[0], blo, bhi)
    int p = 0;
    for (int k0 = 0; k0 < Dd; k0 += 16) {
        bool nxt = (k0 + 16 < Dd);
        if (nxt) { LOAD_ROWMAJ(k0 + 16) LOAD_KMAJ(blo, bhi, Bbase, Mm, k0 + 16) }
        __syncthreads();
        COMPUTE16(sA[p], sB[p])
        if (nxt) { STORE_ROWMAJ(sA[p ^ 1]) STORE_KMAJ(sB[p ^ 1], blo, bhi) }
        p ^= 1;
    }
    float cs[4][2];
#pragma unroll
    for (int nt = 0; nt < 4; nt++) { cs[nt][0] = 0.f; cs[nt][1] = 0.f; }
#pragma unroll
    for (int mt = 0; mt < 4; mt++) {
        int row = n0 + wm * 64 + mt * 16 + lg;
#pragma unroll
        for (int nt = 0; nt < 4; nt++) {
            int col = c0 + wn * 32 + nt * 8 + lt * 2;
            float e0 = __expf(acc[mt][nt][0]);
            float e1 = __expf(acc[mt][nt][1]);
            float e2 = __expf(acc[mt][nt][2]);
            float e3 = __expf(acc[mt][nt][3]);
            *(float2*)(g_e + ((size_t)b * Nn + row) * Mm + col) = make_float2(e0, e1);
            *(float2*)(g_e + ((size_t)b * Nn + row + 8) * Mm + col) = make_float2(e2, e3);
            cs[nt][0] += e0 + e2;
            cs[nt][1] += e1 + e3;
        }
    }
#pragma unroll
    for (int nt = 0; nt < 4; nt++)
#pragma unroll
        for (int pp = 0; pp < 2; pp++) {
            float v = cs[nt][pp];
            v += __shfl_xor_sync(0xffffffffu, v, 4);
            v += __shfl_xor_sync(0xffffffffu, v, 8);
            v += __shfl_xor_sync(0xffffffffu, v, 16);
            if (lg == 0)
                atomicAdd(&g_s[b * Mm + c0 + wn * 32 + nt * 8 + lt * 2 + pp], v);
        }
}

// ---------------- K4: out[...,:512] = (e^T @ features) / s ----------------
__global__ __launch_bounds__(256, 2)
void k_out(const float* __restrict__ feat, float* __restrict__ out) {
    __shared__ u32 sA[2][8 * SST], sB[2][8 * SST];
    GEMM_DECLS
    int b = blockIdx.z;
    int m0 = blockIdx.y * 128;  // GEMM-M (over M)
    int d0 = blockIdx.x * 128;  // GEMM-N (over D)
    const float* Abase = g_e + (size_t)b * Nn * Mm + m0;   // k-major, ld=Mm
    const float* Bbase = feat + (size_t)b * Nn * Dd + d0;  // k-major, ld=Dd
    float4 alo, ahi, blo, bhi;
    LOAD_KMAJ(alo, ahi, Abase, Mm, 0) LOAD_KMAJ(blo, bhi, Bbase, Dd, 0)
    STORE_KMAJ(sA[0], alo, ahi) STORE_KMAJ(sB[0], blo, bhi)
    int p = 0;
    for (int k0 = 0; k0 < Nn; k0 += 16) {
        bool nxt = (k0 + 16 < Nn);
        if (nxt) { LOAD_KMAJ(alo, ahi, Abase, Mm, k0 + 16)
                   LOAD_KMAJ(blo, bhi, Bbase, Dd, k0 + 16) }
        __syncthreads();
        COMPUTE16(sA[p], sB[p])
        if (nxt) { STORE_KMAJ(sA[p ^ 1], alo, ahi) STORE_KMAJ(sB[p ^ 1], blo, bhi) }
        p ^= 1;
    }
#pragma unroll
    for (int mt = 0; mt < 4; mt++) {
        int row = m0 + wm * 64 + mt * 16 + lg;
        float i0 = 1.f / g_s[b * Mm + row];
        float i1 = 1.f / g_s[b * Mm + row + 8];
#pragma unroll
        for (int nt = 0; nt < 4; nt++) {
            int col = d0 + wn * 32 + nt * 8 + lt * 2;
            *(float2*)(out + ((size_t)(b * Mm + row)) * (2 * Dd) + col) =
                make_float2(acc[mt][nt][0] * i0, acc[mt][nt][1] * i0);
            *(float2*)(out + ((size_t)(b * Mm + row + 8)) * (2 * Dd) + col) =
                make_float2(acc[mt][nt][2] * i1, acc[mt][nt][3] * i1);
        }
    }
}

// ---------------- launch ----------------
extern "C" void kernel_launch(void* const* d_in, const int* in_sizes, int n_in,
                              void* d_out, int out_size) {
    const float* features = (const float*)d_in[0];
    const float* text     = (const float*)d_in[1];
    const float* W        = (const float*)d_in[2];
    const float* bias     = (const float*)d_in[3];
    float* out = (float*)d_out;

    k_zero_s<<<(Bb * Mm + 255) / 256, 256>>>();
    k_text<<<Mm, 128>>>(text, out);
    k_linear<<<dim3(Dd / 128, (Bb * Nn) / 128), 256>>>(features, W, bias);
    k_normrows<<<Bb * Nn, 128>>>();
    k_sim<<<dim3(Mm / 128, Nn / 128, Bb), 256>>>();
    k_out<<<dim3(Dd / 128, Mm / 128, Bb), 256>>>(features, out);
}

// round 4
// speedup vs baseline: 5.2356x; 1.5714x over previous
#include <cuda_runtime.h>
#include <cuda_bf16.h>
#include <math.h>

#define Bb 8
#define Nn 4096
#define Mm 2048
#define Dd 512
#define SST 136   // smem word stride; SST%32==8 -> fragment LDS conflict-free
typedef unsigned u32;

// ---------------- scratch (all bf16, stored as packed u32 words) ----------
__device__ u32 g_fnh[(size_t)Bb * Nn * Dd / 2];   // fn, (d,d+1) packed   33.5 MB
__device__ u32 g_tnTh[(size_t)(Dd / 2) * Mm];     // tn^T, (d,d+1) packed  2 MB
__device__ u32 g_eh[(size_t)Bb * Nn * Mm / 2];    // e, (m,m+1) packed   134 MB
__device__ u32 g_fTh[(size_t)Bb * (Nn / 2) * Dd]; // feat, (n,n+1) packed 33.5 MB
__device__ float g_s[Bb * Mm];

__device__ __forceinline__ u32 pk2(float lo, float hi) {
    __nv_bfloat162 h = __floats2bfloat162_rn(lo, hi);
    return *(u32*)&h;
}
__device__ __forceinline__ float2 up2(u32 w) {
    __nv_bfloat162 h = *(__nv_bfloat162*)&w;
    return make_float2(__bfloat162float(h.x), __bfloat162float(h.y));
}

__device__ __forceinline__ void mma_bf16(float& d0, float& d1, float& d2, float& d3,
                                         u32 a0, u32 a1, u32 a2, u32 a3,
                                         u32 b0, u32 b1) {
    asm volatile(
        "mma.sync.aligned.m16n8k16.row.col.f32.bf16.bf16.f32 "
        "{%0,%1,%2,%3}, {%4,%5,%6,%7}, {%8,%9}, {%0,%1,%2,%3};"
        : "+f"(d0), "+f"(d1), "+f"(d2), "+f"(d3)
        : "r"(a0), "r"(a1), "r"(a2), "r"(a3), "r"(b0), "r"(b1));
}

// ---------------- K0: zero sums ----------------
__global__ void k_zero_s() {
    int i = blockIdx.x * 256 + threadIdx.x;
    if (i < Bb * Mm) g_s[i] = 0.f;
}

// ---------------- K1: text row 1 -> g_tnTh (normalized); raw t1 -> out ----
__global__ void k_text(const float* __restrict__ text, float* __restrict__ out) {
    int m = blockIdx.x, tid = threadIdx.x;
    const float4* t1 = (const float4*)(text + (size_t)Mm * Dd + (size_t)m * Dd);
    float4 v = t1[tid];
    float ss = v.x * v.x + v.y * v.y + v.z * v.z + v.w * v.w;
#pragma unroll
    for (int o = 16; o > 0; o >>= 1) ss += __shfl_xor_sync(0xffffffffu, ss, o);
    __shared__ float ws[4];
    if ((tid & 31) == 0) ws[tid >> 5] = ss;
    __syncthreads();
    float inv = 1.f / fmaxf(sqrtf(ws[0] + ws[1] + ws[2] + ws[3]), 1e-8f);
    int dw = tid * 2;  // word index along d
    g_tnTh[(size_t)(dw + 0) * Mm + m] = pk2(v.x * inv, v.y * inv);
    g_tnTh[(size_t)(dw + 1) * Mm + m] = pk2(v.z * inv, v.w * inv);
#pragma unroll
    for (int b = 0; b < Bb; b++) {
        float4* o = (float4*)(out + ((size_t)(b * Mm + m)) * (2 * Dd) + Dd);
        o[tid] = v;
    }
}

// ---------------- K1b: repack features -> g_fTh ((n,n+1) pairs) ----------
__global__ void k_prepfeat(const float* __restrict__ feat) {
    int t = blockIdx.x * 256 + threadIdx.x;        // 0 .. B*N/2*D/4-1
    int d4 = (t & (Dd / 4 - 1)) * 4;
    size_t rp = (size_t)(t >> 7);                  // row-pair: b*(N/2)+np
    float4 lo = *(const float4*)(feat + rp * 2 * Dd + d4);
    float4 hi = *(const float4*)(feat + (rp * 2 + 1) * Dd + d4);
    *(uint4*)(g_fTh + rp * Dd + d4) = make_uint4(
        pk2(lo.x, hi.x), pk2(lo.y, hi.y), pk2(lo.z, hi.z), pk2(lo.w, hi.w));
}

// ---------------- K2b: row-normalize g_fnh in place (bf16) --------------
__global__ void k_normrows() {
    int r = blockIdx.x, tid = threadIdx.x;
    u32* row = g_fnh + (size_t)r * (Dd / 2);
    uint2 w = *(uint2*)(row + tid * 2);
    float2 a = up2(w.x), b = up2(w.y);
    float ss = a.x * a.x + a.y * a.y + b.x * b.x + b.y * b.y;
#pragma unroll
    for (int o = 16; o > 0; o >>= 1) ss += __shfl_xor_sync(0xffffffffu, ss, o);
    __shared__ float ws[4];
    if ((tid & 31) == 0) ws[tid >> 5] = ss;
    __syncthreads();
    float inv = 1.f / fmaxf(sqrtf(ws[0] + ws[1] + ws[2] + ws[3]), 1e-8f);
    *(uint2*)(row + tid * 2) = make_uint2(pk2(a.x * inv, a.y * inv),
                                          pk2(b.x * inv, b.y * inv));
}

// ================= bf16 GEMM framework =================
#define GEMM_DECLS                                                         \
    int tid = threadIdx.x, lane = tid & 31, warp = tid >> 5;               \
    int wm = warp >> 2, wn = warp & 3;                                     \
    int lg = lane >> 2, lt = lane & 3;                                     \
    float acc[4][4][4];                                                    \
    _Pragma("unroll") for (int i = 0; i < 4; i++)                          \
    _Pragma("unroll") for (int j = 0; j < 4; j++)                          \
    _Pragma("unroll") for (int r = 0; r < 4; r++) acc[i][j][r] = 0.f;

#define COMPUTE16(sAp, sBp)                                                \
    { u32 bf[4][2];                                                        \
      _Pragma("unroll") for (int nt = 0; nt < 4; nt++) {                   \
          int nb = wn * 32 + nt * 8 + lg;                                  \
          bf[nt][0] = sBp[lt * SST + nb];                                  \
          bf[nt][1] = sBp[(lt + 4) * SST + nb]; }                          \
      _Pragma("unroll") for (int mt = 0; mt < 4; mt++) {                   \
          int mb = wm * 64 + mt * 16 + lg;                                 \
          u32 a0 = sAp[lt * SST + mb];                                     \
          u32 a1 = sAp[lt * SST + mb + 8];                                 \
          u32 a2 = sAp[(lt + 4) * SST + mb];                               \
          u32 a3 = sAp[(lt + 4) * SST + mb + 8];                           \
          _Pragma("unroll") for (int nt = 0; nt < 4; nt++)                 \
              mma_bf16(acc[mt][nt][0], acc[mt][nt][1],                     \
                       acc[mt][nt][2], acc[mt][nt][3],                     \
                       a0, a1, a2, a3, bf[nt][0], bf[nt][1]); } }

// ---------------- K2a: fn_raw = feat @ W + b -> g_fnh (fp32 in, bf16 out) --
// A row-major fp32, B (W) k-major fp32.
__global__ __launch_bounds__(256, 2)
void k_linear(const float* __restrict__ A, const float* __restrict__ W,
              const float* __restrict__ bias) {
    __shared__ u32 sA[2][8 * SST], sB[2][8 * SST];
    GEMM_DECLS
    int m0 = blockIdx.y * 128, n0 = blockIdx.x * 128;
    const float* Abase = A + (size_t)m0 * Dd;
    const float* Bbase = W + n0;
    float4 ra[2], blo, bhi;

#define LIN_LOAD(k0)                                                       \
    _Pragma("unroll") for (int i = 0; i < 2; i++) {                        \
        int f = tid * 2 + i;                                               \
        ra[i] = *(const float4*)(Abase + (size_t)(f >> 2) * Dd + (k0) + (f & 3) * 4); } \
    { int kw = tid >> 5, c4 = (tid & 31) * 4;                              \
      blo = *(const float4*)(Bbase + (size_t)((k0) + 2 * kw) * Dd + c4);   \
      bhi = *(const float4*)(Bbase + (size_t)((k0) + 2 * kw + 1) * Dd + c4); }
#define LIN_STORE(p)                                                       \
    _Pragma("unroll") for (int i = 0; i < 2; i++) {                        \
        int f = tid * 2 + i; int row = f >> 2, kw = (f & 3) * 2;           \
        sA[p][kw * SST + row]       = pk2(ra[i].x, ra[i].y);               \
        sA[p][(kw + 1) * SST + row] = pk2(ra[i].z, ra[i].w); }             \
    { int kw = tid >> 5, c4 = (tid & 31) * 4;                              \
      *(uint4*)(sB[p] + kw * SST + c4) = make_uint4(                       \
          pk2(blo.x, bhi.x), pk2(blo.y, bhi.y), pk2(blo.z, bhi.z), pk2(blo.w, bhi.w)); }

    LIN_LOAD(0) LIN_STORE(0)
    int p = 0;
    for (int k0 = 0; k0 < Dd; k0 += 16) {
        bool nxt = (k0 + 16 < Dd);
        if (nxt) { LIN_LOAD(k0 + 16) }
        __syncthreads();
        COMPUTE16(sA[p], sB[p])
        if (nxt) { LIN_STORE(p ^ 1) }
        p ^= 1;
    }
#pragma unroll
    for (int mt = 0; mt < 4; mt++) {
        int row = m0 + wm * 64 + mt * 16 + lg;
#pragma unroll
        for (int nt = 0; nt < 4; nt++) {
            int col = n0 + wn * 32 + nt * 8 + lt * 2;
            float b0 = bias[col], b1 = bias[col + 1];
            g_fnh[((size_t)row * Dd + col) >> 1] =
                pk2(acc[mt][nt][0] + b0, acc[mt][nt][1] + b1);
            g_fnh[((size_t)(row + 8) * Dd + col) >> 1] =
                pk2(acc[mt][nt][2] + b0, acc[mt][nt][3] + b1);
        }
    }
}

// ---------------- K3: e = exp(fn @ tnT) -> g_eh; col sums -> g_s ----------
__global__ __launch_bounds__(256, 2)
void k_sim() {
    __shared__ u32 sA[2][8 * SST], sB[2][8 * SST];
    GEMM_DECLS
    int b = blockIdx.z;
    int n0 = blockIdx.y * 128;  // GEMM-M (over N)
    int c0 = blockIdx.x * 128;  // GEMM-N (over M)
    const u32* Abase = g_fnh + ((size_t)b * Nn + n0) * (Dd / 2);
    uint4 rav, rbv;

#define SIM_LOAD(k0)                                                       \
    { int row = tid >> 1, kw4 = (tid & 1) * 4;                             \
      rav = *(const uint4*)(Abase + (size_t)row * (Dd / 2) + (k0) / 2 + kw4); } \
    { int kw = tid >> 5, m4 = (tid & 31) * 4;                              \
      rbv = *(const uint4*)(g_tnTh + (size_t)((k0) / 2 + kw) * Mm + c0 + m4); }
#define SIM_STORE(p)                                                       \
    { int row = tid >> 1, kw4 = (tid & 1) * 4;                             \
      sA[p][(kw4 + 0) * SST + row] = rav.x;                                \
      sA[p][(kw4 + 1) * SST + row] = rav.y;                                \
      sA[p][(kw4 + 2) * SST + row] = rav.z;                                \
      sA[p][(kw4 + 3) * SST + row] = rav.w; }                              \
    { int kw = tid >> 5, m4 = (tid & 31) * 4;                              \
      *(uint4*)(sB[p] + kw * SST + m4) = rbv; }

    SIM_LOAD(0) SIM_STORE(0)
    int p = 0;
    for (int k0 = 0; k0 < Dd; k0 += 16) {
        bool nxt = (k0 + 16 < Dd);
        if (nxt) { SIM_LOAD(k0 + 16) }
        __syncthreads();
        COMPUTE16(sA[p], sB[p])
        if (nxt) { SIM_STORE(p ^ 1) }
        p ^= 1;
    }
    float cs[4][2];
#pragma unroll
    for (int nt = 0; nt < 4; nt++) { cs[nt][0] = 0.f; cs[nt][1] = 0.f; }
#pragma unroll
    for (int mt = 0; mt < 4; mt++) {
        int row = n0 + wm * 64 + mt * 16 + lg;
#pragma unroll
        for (int nt = 0; nt < 4; nt++) {
            int col = c0 + wn * 32 + nt * 8 + lt * 2;
            float e0 = __expf(acc[mt][nt][0]);
            float e1 = __expf(acc[mt][nt][1]);
            float e2 = __expf(acc[mt][nt][2]);
            float e3 = __expf(acc[mt][nt][3]);
            g_eh[((size_t)b * Nn + row) * Mm + col >> 1] = pk2(e0, e1);
            g_eh[(((size_t)b * Nn + row + 8) * Mm + col) >> 1] = pk2(e2, e3);
            cs[nt][0] += e0 + e2;
            cs[nt][1] += e1 + e3;
        }
    }
#pragma unroll
    for (int nt = 0; nt < 4; nt++)
#pragma unroll
        for (int pp = 0; pp < 2; pp++) {
            float v = cs[nt][pp];
            v += __shfl_xor_sync(0xffffffffu, v, 4);
            v += __shfl_xor_sync(0xffffffffu, v, 8);
            v += __shfl_xor_sync(0xffffffffu, v, 16);
            if (lg == 0)
                atomicAdd(&g_s[b * Mm + c0 + wn * 32 + nt * 8 + lt * 2 + pp], v);
        }
}

// ---------------- K4: out[...,:512] = (e^T @ feat) / s --------------------
__global__ __launch_bounds__(256, 2)
void k_out(float* __restrict__ out) {
    __shared__ u32 sA[2][8 * SST], sB[2][8 * SST];
    GEMM_DECLS
    int b = blockIdx.z;
    int m0 = blockIdx.y * 128;  // GEMM-M (over M)
    int d0 = blockIdx.x * 128;  // GEMM-N (over D)
    // A: g_eh bf16 [n][m]; pack (n,n+1) pairs. word row stride = Mm/2.
    const u32* Ab = g_eh + (size_t)b * Nn * (Mm / 2) + (m0 >> 1);
    const u32* Bbw = g_fTh + (size_t)b * (Nn / 2) * Dd + d0;
    uint2 ralo, rahi;
    uint4 rbv;

#define OUT_LOAD(k0)                                                       \
    { int kw = tid >> 5, m4 = (tid & 31) * 4;                              \
      ralo = *(const uint2*)(Ab + (size_t)((k0) + 2 * kw) * (Mm / 2) + (m4 >> 1));      \
      rahi = *(const uint2*)(Ab + (size_t)((k0) + 2 * kw + 1) * (Mm / 2) + (m4 >> 1));  \
      rbv = *(const uint4*)(Bbw + (size_t)((k0) / 2 + kw) * Dd + m4); }
#define OUT_STORE(p)                                                       \
    { int kw = tid >> 5, m4 = (tid & 31) * 4;                              \
      *(uint4*)(sA[p] + kw * SST + m4) = make_uint4(                       \
          __byte_perm(ralo.x, rahi.x, 0x5410), __byte_perm(ralo.x, rahi.x, 0x7632), \
          __byte_perm(ralo.y, rahi.y, 0x5410), __byte_perm(ralo.y, rahi.y, 0x7632)); \
      *(uint4*)(sB[p] + kw * SST + m4) = rbv; }

    OUT_LOAD(0) OUT_STORE(0)
    int p = 0;
    for (int k0 = 0; k0 < Nn; k0 += 16) {
        bool nxt = (k0 + 16 < Nn);
        if (nxt) { OUT_LOAD(k0 + 16) }
        __syncthreads();
        COMPUTE16(sA[p], sB[p])
        if (nxt) { OUT_STORE(p ^ 1) }
        p ^= 1;
    }
#pragma unroll
    for (int mt = 0; mt < 4; mt++) {
        int row = m0 + wm * 64 + mt * 16 + lg;
        float i0 = 1.f / g_s[b * Mm + row];
        float i1 = 1.f / g_s[b * Mm + row + 8];
#pragma unroll
        for (int nt = 0; nt < 4; nt++) {
            int col = d0 + wn * 32 + nt * 8 + lt * 2;
            *(float2*)(out + ((size_t)(b * Mm + row)) * (2 * Dd) + col) =
                make_float2(acc[mt][nt][0] * i0, acc[mt][nt][1] * i0);
            *(float2*)(out + ((size_t)(b * Mm + row + 8)) * (2 * Dd) + col) =
                make_float2(acc[mt][nt][2] * i1, acc[mt][nt][3] * i1);
        }
    }
}

// ---------------- launch ----------------
extern "C" void kernel_launch(void* const* d_in, const int* in_sizes, int n_in,
                              void* d_out, int out_size) {
    const float* features = (const float*)d_in[0];
    const float* text     = (const float*)d_in[1];
    const float* W        = (const float*)d_in[2];
    const float* bias     = (const float*)d_in[3];
    float* out = (float*)d_out;

    k_zero_s<<<(Bb * Mm + 255) / 256, 256>>>();
    k_text<<<Mm, 128>>>(text, out);
    k_prepfeat<<<(Bb * (Nn / 2) * (Dd / 4)) / 256, 256>>>(features);
    k_linear<<<dim3(Dd / 128, (Bb * Nn) / 128), 256>>>(features, W, bias);
    k_normrows<<<Bb * Nn, 128>>>();
    k_sim<<<dim3(Mm / 128, Nn / 128, Bb), 256>>>();
    k_out<<<dim3(Dd / 128, Mm / 128, Bb), 256>>>(out);
}

// round 5
// speedup vs baseline: 5.4578x; 1.0424x over previous
#include <cuda_runtime.h>
#include <cuda_bf16.h>
#include <math.h>

#define Bb 8
#define Nn 4096
#define Mm 2048
#define Dd 512
typedef unsigned u32;

// ---------------- scratch (bf16 packed words) ----------------
__device__ u32 g_fnh[(size_t)Bb * Nn * (Dd / 2)];   // fn rows, (d,d+1) packed
__device__ u32 g_tnh[(size_t)Mm * (Dd / 2)];        // tn rows, (d,d+1) packed
__device__ u32 g_eth[(size_t)Bb * Mm * (Nn / 2)];   // e^T: [b][m][(n,n+1)]
__device__ u32 g_fTh[(size_t)Bb * Dd * (Nn / 2)];   // feat^T: [b][d][(n,n+1)]
__device__ float g_s[Bb * Mm];

__device__ __forceinline__ u32 pk2(float lo, float hi) {
    __nv_bfloat162 h = __floats2bfloat162_rn(lo, hi);
    return *(u32*)&h;
}
__device__ __forceinline__ float2 up2(u32 w) {
    __nv_bfloat162 h = *(__nv_bfloat162*)&w;
    return make_float2(__bfloat162float(h.x), __bfloat162float(h.y));
}
__device__ __forceinline__ u32 s2u(const void* p) {
    return (u32)__cvta_generic_to_shared(p);
}
__device__ __forceinline__ void ldsm4(u32& r0, u32& r1, u32& r2, u32& r3, u32 addr) {
    asm volatile("ldmatrix.sync.aligned.m8n8.x4.shared.b16 {%0,%1,%2,%3}, [%4];"
                 : "=r"(r0), "=r"(r1), "=r"(r2), "=r"(r3) : "r"(addr));
}
__device__ __forceinline__ void mma_bf16(float& d0, float& d1, float& d2, float& d3,
                                         u32 a0, u32 a1, u32 a2, u32 a3,
                                         u32 b0, u32 b1) {
    asm volatile(
        "mma.sync.aligned.m16n8k16.row.col.f32.bf16.bf16.f32 "
        "{%0,%1,%2,%3}, {%4,%5,%6,%7}, {%8,%9}, {%0,%1,%2,%3};"
        : "+f"(d0), "+f"(d1), "+f"(d2), "+f"(d3)
        : "r"(a0), "r"(a1), "r"(a2), "r"(a3), "r"(b0), "r"(b1));
}

// ---------------- small kernels ----------------
__global__ void k_zero_s() {
    int i = blockIdx.x * 256 + threadIdx.x;
    if (i < Bb * Mm) g_s[i] = 0.f;
}

__global__ void k_text(const float* __restrict__ text, float* __restrict__ out) {
    int m = blockIdx.x, tid = threadIdx.x;
    const float4* t1 = (const float4*)(text + (size_t)Mm * Dd + (size_t)m * Dd);
    float4 v = t1[tid];
    float ss = v.x * v.x + v.y * v.y + v.z * v.z + v.w * v.w;
#pragma unroll
    for (int o = 16; o > 0; o >>= 1) ss += __shfl_xor_sync(0xffffffffu, ss, o);
    __shared__ float ws[4];
    if ((tid & 31) == 0) ws[tid >> 5] = ss;
    __syncthreads();
    float inv = 1.f / fmaxf(sqrtf(ws[0] + ws[1] + ws[2] + ws[3]), 1e-8f);
    *(uint2*)(g_tnh + (size_t)m * (Dd / 2) + tid * 2) =
        make_uint2(pk2(v.x * inv, v.y * inv), pk2(v.z * inv, v.w * inv));
#pragma unroll
    for (int b = 0; b < Bb; b++) {
        float4* o = (float4*)(out + ((size_t)(b * Mm + m)) * (2 * Dd) + Dd);
        o[tid] = v;
    }
}

// transpose-pack features -> g_fTh[b][d][(n,n+1)]
__global__ void k_prepfeat(const float* __restrict__ feat) {
    __shared__ float sm[64][65];
    int b = blockIdx.z, d0 = blockIdx.y * 64, n0 = blockIdx.x * 64;
    int t = threadIdx.x;
    int lr = t >> 4, lc = (t & 15) * 4;
#pragma unroll
    for (int r = 0; r < 4; r++) {
        float4 v = *(const float4*)(feat + ((size_t)b * Nn + n0 + lr + r * 16) * Dd + d0 + lc);
        sm[lr + r * 16][lc + 0] = v.x;
        sm[lr + r * 16][lc + 1] = v.y;
        sm[lr + r * 16][lc + 2] = v.z;
        sm[lr + r * 16][lc + 3] = v.w;
    }
    __syncthreads();
    int d = t >> 2, npb = (t & 3) * 8;
    u32 w[8];
#pragma unroll
    for (int j = 0; j < 8; j++) {
        int np = npb + j;
        w[j] = pk2(sm[2 * np][d], sm[2 * np + 1][d]);
    }
    u32* dst = g_fTh + ((size_t)b * Dd + d0 + d) * (Nn / 2) + n0 / 2 + npb;
    *(uint4*)dst = make_uint4(w[0], w[1], w[2], w[3]);
    *(uint4*)(dst + 4) = make_uint4(w[4], w[5], w[6], w[7]);
}

__global__ void k_normrows() {
    int r = blockIdx.x, tid = threadIdx.x;
    u32* row = g_fnh + (size_t)r * (Dd / 2);
    uint2 w = *(uint2*)(row + tid * 2);
    float2 a = up2(w.x), b = up2(w.y);
    float ss = a.x * a.x + a.y * a.y + b.x * b.x + b.y * b.y;
#pragma unroll
    for (int o = 16; o > 0; o >>= 1) ss += __shfl_xor_sync(0xffffffffu, ss, o);
    __shared__ float ws[4];
    if ((tid & 31) == 0) ws[tid >> 5] = ss;
    __syncthreads();
    float inv = 1.f / fmaxf(sqrtf(ws[0] + ws[1] + ws[2] + ws[3]), 1e-8f);
    *(uint2*)(row + tid * 2) = make_uint2(pk2(a.x * inv, a.y * inv),
                                          pk2(b.x * inv, b.y * inv));
}

// ================= ldmatrix GEMM framework =================
// smem per operand stage: [128 rows][8 words], 32B rows,
// chunk swizzle: phys_chunk = chunk ^ ((row>>2)&1).

#define GEMM_DECLS                                                          \
    int tid = threadIdx.x, lane = tid & 31, warp = tid >> 5;                \
    int wm = warp >> 2, wn = warp & 3;                                      \
    int lg = lane >> 2, lt = lane & 3;                                      \
    int rowA = wm * 64 + (lane & 15);                                       \
    u32 aoff = (u32)((rowA * 8 + (((lane >> 4) ^ ((rowA >> 2) & 1)) * 4)) * 4); \
    int rowB = wn * 32 + (lane & 7) + ((lane >> 4) << 3);                   \
    u32 boff = (u32)((rowB * 8 + ((((lane >> 3) & 1) ^ ((rowB >> 2) & 1)) * 4)) * 4); \
    int srow = tid >> 1;                                                    \
    u32 stByte = (u32)((srow * 8 + (((tid & 1) ^ ((srow >> 2) & 1)) * 4)) * 4); \
    float acc[4][4][4];                                                     \
    _Pragma("unroll") for (int i = 0; i < 4; i++)                           \
    _Pragma("unroll") for (int j = 0; j < 4; j++)                           \
    _Pragma("unroll") for (int r = 0; r < 4; r++) acc[i][j][r] = 0.f;

#define COMPUTE16(aB, bB) {                                                 \
    u32 af[4][4], bq[2][4];                                                 \
    _Pragma("unroll") for (int mt = 0; mt < 4; mt++)                        \
        ldsm4(af[mt][0], af[mt][1], af[mt][2], af[mt][3],                   \
              (aB) + aoff + mt * 512);                                      \
    _Pragma("unroll") for (int pq = 0; pq < 2; pq++)                        \
        ldsm4(bq[pq][0], bq[pq][1], bq[pq][2], bq[pq][3],                   \
              (bB) + boff + pq * 512);                                      \
    _Pragma("unroll") for (int mt = 0; mt < 4; mt++)                        \
        _Pragma("unroll") for (int nt = 0; nt < 4; nt++)                    \
            mma_bf16(acc[mt][nt][0], acc[mt][nt][1],                        \
                     acc[mt][nt][2], acc[mt][nt][3],                        \
                     af[mt][0], af[mt][1], af[mt][2], af[mt][3],            \
                     bq[nt >> 1][(nt & 1) * 2], bq[nt >> 1][(nt & 1) * 2 + 1]); }

// uint4 tile load from packed-word row-major source (srcbase at block row 0)
#define LOADW(rv, srcbase, rowwords, k0)                                    \
    rv = *(const uint4*)((srcbase) + (size_t)srow * (rowwords) + (k0) / 2 + (tid & 1) * 4);
#define STOREW(stagePtr, rv) *(uint4*)((char*)(stagePtr) + stByte) = rv;

// ---------------- K2a: fn_raw = feat @ W + b -> g_fnh ----------------
__global__ __launch_bounds__(256, 2)
void k_linear(const float* __restrict__ A, const float* __restrict__ W,
              const float* __restrict__ bias) {
    __shared__ __align__(16) u32 sA[2][1024], sB[2][1024];
    GEMM_DECLS
    u32 sAu[2] = {s2u(sA[0]), s2u(sA[1])};
    u32 sBu[2] = {s2u(sB[0]), s2u(sB[1])};
    int m0 = blockIdx.y * 128, n0 = blockIdx.x * 128;
    const float* Abase = A + (size_t)m0 * Dd;
    float4 alo, ahi;
    float bw[8];

#define LIN_LOAD(k0)                                                        \
    { alo = *(const float4*)(Abase + (size_t)srow * Dd + (k0) + (tid & 1) * 8);       \
      ahi = *(const float4*)(Abase + (size_t)srow * Dd + (k0) + (tid & 1) * 8 + 4);   \
      _Pragma("unroll") for (int j = 0; j < 8; j++)                         \
          bw[j] = W[(size_t)((k0) + (tid & 1) * 8 + j) * Dd + n0 + srow]; }
#define LIN_STORE(p)                                                        \
    { uint4 rv = make_uint4(pk2(alo.x, alo.y), pk2(alo.z, alo.w),           \
                            pk2(ahi.x, ahi.y), pk2(ahi.z, ahi.w));          \
      STOREW(sA[p], rv)                                                     \
      uint4 rb = make_uint4(pk2(bw[0], bw[1]), pk2(bw[2], bw[3]),           \
                            pk2(bw[4], bw[5]), pk2(bw[6], bw[7]));          \
      STOREW(sB[p], rb) }

    LIN_LOAD(0) LIN_STORE(0)
    int p = 0;
    for (int k0 = 0; k0 < Dd; k0 += 16) {
        bool nxt = (k0 + 16 < Dd);
        if (nxt) { LIN_LOAD(k0 + 16) }
        __syncthreads();
        COMPUTE16(sAu[p], sBu[p])
        if (nxt) { LIN_STORE(p ^ 1) }
        p ^= 1;
    }
#pragma unroll
    for (int mt = 0; mt < 4; mt++) {
        int row = m0 + wm * 64 + mt * 16 + lg;
#pragma unroll
        for (int nt = 0; nt < 4; nt++) {
            int col = n0 + wn * 32 + nt * 8 + lt * 2;
            float b0 = bias[col], b1 = bias[col + 1];
            g_fnh[((size_t)row * Dd + col) >> 1] =
                pk2(acc[mt][nt][0] + b0, acc[mt][nt][1] + b1);
            g_fnh[((size_t)(row + 8) * Dd + col) >> 1] =
                pk2(acc[mt][nt][2] + b0, acc[mt][nt][3] + b1);
        }
    }
}

// ---------------- K3: e^T = exp(tn @ fn^T) -> g_eth; row sums -> g_s ------
__global__ __launch_bounds__(256, 2)
void k_sim() {
    __shared__ __align__(16) u32 sA[2][1024], sB[2][1024];
    GEMM_DECLS
    u32 sAu[2] = {s2u(sA[0]), s2u(sA[1])};
    u32 sBu[2] = {s2u(sB[0]), s2u(sB[1])};
    int b = blockIdx.z;
    int m0 = blockIdx.y * 128;  // GEMM-M over Mm
    int n0 = blockIdx.x * 128;  // GEMM-N over Nn
    const u32* Abase = g_tnh + (size_t)m0 * (Dd / 2);
    const u32* Bbase = g_fnh + ((size_t)b * Nn + n0) * (Dd / 2);
    uint4 rav, rbv;
    LOADW(rav, Abase, Dd / 2, 0) LOADW(rbv, Bbase, Dd / 2, 0)
    STOREW(sA[0], rav) STOREW(sB[0], rbv)
    int p = 0;
    for (int k0 = 0; k0 < Dd; k0 += 16) {
        bool nxt = (k0 + 16 < Dd);
        if (nxt) { LOADW(rav, Abase, Dd / 2, k0 + 16) LOADW(rbv, Bbase, Dd / 2, k0 + 16) }
        __syncthreads();
        COMPUTE16(sAu[p], sBu[p])
        if (nxt) { STOREW(sA[p ^ 1], rav) STOREW(sB[p ^ 1], rbv) }
        p ^= 1;
    }
    float rs[4][2];
#pragma unroll
    for (int mt = 0; mt < 4; mt++) { rs[mt][0] = 0.f; rs[mt][1] = 0.f; }
#pragma unroll
    for (int mt = 0; mt < 4; mt++) {
        int m = m0 + wm * 64 + mt * 16 + lg;
#pragma unroll
        for (int nt = 0; nt < 4; nt++) {
            int nw = (n0 + wn * 32 + nt * 8 + lt * 2) >> 1;
            float e0 = __expf(acc[mt][nt][0]);
            float e1 = __expf(acc[mt][nt][1]);
            float e2 = __expf(acc[mt][nt][2]);
            float e3 = __expf(acc[mt][nt][3]);
            g_eth[((size_t)b * Mm + m) * (Nn / 2) + nw] = pk2(e0, e1);
            g_eth[((size_t)b * Mm + m + 8) * (Nn / 2) + nw] = pk2(e2, e3);
            rs[mt][0] += e0 + e1;
            rs[mt][1] += e2 + e3;
        }
    }
#pragma unroll
    for (int mt = 0; mt < 4; mt++)
#pragma unroll
        for (int r = 0; r < 2; r++) {
            float v = rs[mt][r];
            v += __shfl_xor_sync(0xffffffffu, v, 1);
            v += __shfl_xor_sync(0xffffffffu, v, 2);
            if (lt == 0)
                atomicAdd(&g_s[b * Mm + m0 + wm * 64 + mt * 16 + lg + r * 8], v);
        }
}

// ---------------- K4: out[...,:512] = (e @ featT^T) / s ------------------
__global__ __launch_bounds__(256, 2)
void k_out(float* __restrict__ out) {
    __shared__ __align__(16) u32 sA[2][1024], sB[2][1024];
    GEMM_DECLS
    u32 sAu[2] = {s2u(sA[0]), s2u(sA[1])};
    u32 sBu[2] = {s2u(sB[0]), s2u(sB[1])};
    int b = blockIdx.z;
    int m0 = blockIdx.y * 128;  // GEMM-M over Mm
    int d0 = blockIdx.x * 128;  // GEMM-N over Dd
    const u32* Abase = g_eth + ((size_t)b * Mm + m0) * (Nn / 2);
    const u32* Bbase = g_fTh + ((size_t)b * Dd + d0) * (Nn / 2);
    uint4 rav, rbv;
    LOADW(rav, Abase, Nn / 2, 0) LOADW(rbv, Bbase, Nn / 2, 0)
    STOREW(sA[0], rav) STOREW(sB[0], rbv)
    int p = 0;
    for (int k0 = 0; k0 < Nn; k0 += 16) {
        bool nxt = (k0 + 16 < Nn);
        if (nxt) { LOADW(rav, Abase, Nn / 2, k0 + 16) LOADW(rbv, Bbase, Nn / 2, k0 + 16) }
        __syncthreads();
        COMPUTE16(sAu[p], sBu[p])
        if (nxt) { STOREW(sA[p ^ 1], rav) STOREW(sB[p ^ 1], rbv) }
        p ^= 1;
    }
#pragma unroll
    for (int mt = 0; mt < 4; mt++) {
        int row = m0 + wm * 64 + mt * 16 + lg;
        float i0 = 1.f / g_s[b * Mm + row];
        float i1 = 1.f / g_s[b * Mm + row + 8];
#pragma unroll
        for (int nt = 0; nt < 4; nt++) {
            int col = d0 + wn * 32 + nt * 8 + lt * 2;
            *(float2*)(out + ((size_t)(b * Mm + row)) * (2 * Dd) + col) =
                make_float2(acc[mt][nt][0] * i0, acc[mt][nt][1] * i0);
            *(float2*)(out + ((size_t)(b * Mm + row + 8)) * (2 * Dd) + col) =
                make_float2(acc[mt][nt][2] * i1, acc[mt][nt][3] * i1);
        }
    }
}

// ---------------- launch ----------------
extern "C" void kernel_launch(void* const* d_in, const int* in_sizes, int n_in,
                              void* d_out, int out_size) {
    const float* features = (const float*)d_in[0];
    const float* text     = (const float*)d_in[1];
    const float* W        = (const float*)d_in[2];
    const float* bias     = (const float*)d_in[3];
    float* out = (float*)d_out;

    k_zero_s<<<(Bb * Mm + 255) / 256, 256>>>();
    k_text<<<Mm, 128>>>(text, out);
    k_prepfeat<<<dim3(Nn / 64, Dd / 64, Bb), 256>>>(features);
    k_linear<<<dim3(Dd / 128, (Bb * Nn) / 128), 256>>>(features, W, bias);
    k_normrows<<<Bb * Nn, 128>>>();
    k_sim<<<dim3(Nn / 128, Mm / 128, Bb), 256>>>();
    k_out<<<dim3(Dd / 128, Mm / 128, Bb), 256>>>(out);
}

// round 7
// speedup vs baseline: 6.9109x; 1.2662x over previous
#include <cuda_runtime.h>
#include <cuda_bf16.h>
#include <math.h>

#define Bb 8
#define Nn 4096
#define Mm 2048
#define Dd 512
typedef unsigned u32;

// ---------------- scratch (bf16 packed words, 16B aligned) ----------------
__device__ __align__(16) u32 g_fh [(size_t)Bb * Nn * (Dd / 2)];  // feat rows bf16
__device__ __align__(16) u32 g_fTh[(size_t)Bb * Dd * (Nn / 2)];  // feat^T bf16
__device__ __align__(16) u32 g_wt [(size_t)Dd * (Dd / 2)];       // W^T rows bf16
__device__ __align__(16) u32 g_tnh[(size_t)Mm * (Dd / 2)];       // tn rows bf16
__device__ __align__(16) u32 g_fnh[(size_t)Bb * Nn * (Dd / 2)];  // f1 (unnormalized) bf16
__device__ __align__(16) u32 g_eth[(size_t)Bb * Mm * (Nn / 2)];  // e^T: [b][m][(n,n+1)]
__device__ float g_s[Bb * Mm];   // softmax denominators
__device__ float g_rn[Bb * Nn];  // per-row |f1|^2

__device__ __forceinline__ u32 pk2(float lo, float hi) {
    __nv_bfloat162 h = __floats2bfloat162_rn(lo, hi);
    return *(u32*)&h;
}
__device__ __forceinline__ u32 s2u(const void* p) {
    return (u32)__cvta_generic_to_shared(p);
}
__device__ __forceinline__ void cpa16(u32 saddr, const void* g) {
    asm volatile("cp.async.cg.shared.global [%0], [%1], 16;" :: "r"(saddr), "l"(g));
}
#define CP_COMMIT asm volatile("cp.async.commit_group;" ::: "memory")
#define CP_WAIT1 asm volatile("cp.async.wait_group 1;" ::: "memory")
__device__ __forceinline__ void ldsm4(u32& r0, u32& r1, u32& r2, u32& r3, u32 addr) {
    asm volatile("ldmatrix.sync.aligned.m8n8.x4.shared.b16 {%0,%1,%2,%3}, [%4];"
                 : "=r"(r0), "=r"(r1), "=r"(r2), "=r"(r3) : "r"(addr));
}
__device__ __forceinline__ void mma_bf16(float& d0, float& d1, float& d2, float& d3,
                                         u32 a0, u32 a1, u32 a2, u32 a3,
                                         u32 b0, u32 b1) {
    asm volatile(
        "mma.sync.aligned.m16n8k16.row.col.f32.bf16.bf16.f32 "
        "{%0,%1,%2,%3}, {%4,%5,%6,%7}, {%8,%9}, {%0,%1,%2,%3};"
        : "+f"(d0), "+f"(d1), "+f"(d2), "+f"(d3)
        : "r"(a0), "r"(a1), "r"(a2), "r"(a3), "r"(b0), "r"(b1));
}

// ---------------- small kernels ----------------
__global__ void k_zero() {
    int i = blockIdx.x * 256 + threadIdx.x;
    if (i < Bb * Mm) g_s[i] = 0.f;
    if (i < Bb * Nn) g_rn[i] = 0.f;
}

__global__ void k_text(const float* __restrict__ text, float* __restrict__ out) {
    int m = blockIdx.x, tid = threadIdx.x;
    const float4* t1 = (const float4*)(text + (size_t)Mm * Dd + (size_t)m * Dd);
    float4 v = t1[tid];
    float ss = v.x * v.x + v.y * v.y + v.z * v.z + v.w * v.w;
#pragma unroll
    for (int o = 16; o > 0; o >>= 1) ss += __shfl_xor_sync(0xffffffffu, ss, o);
    __shared__ float ws[4];
    if ((tid & 31) == 0) ws[tid >> 5] = ss;
    __syncthreads();
    float inv = 1.f / fmaxf(sqrtf(ws[0] + ws[1] + ws[2] + ws[3]), 1e-8f);
    *(uint2*)(g_tnh + (size_t)m * (Dd / 2) + tid * 2) =
        make_uint2(pk2(v.x * inv, v.y * inv), pk2(v.z * inv, v.w * inv));
#pragma unroll
    for (int b = 0; b < Bb; b++) {
        float4* o = (float4*)(out + ((size_t)(b * Mm + m)) * (2 * Dd) + Dd);
        o[tid] = v;
    }
}

// features -> g_fh (row-major bf16) + g_fTh (transpose-pack)
__global__ void k_prepfeat(const float* __restrict__ feat) {
    __shared__ float sm[64][65];
    int b = blockIdx.z, d0 = blockIdx.y * 64, n0 = blockIdx.x * 64;
    int t = threadIdx.x;
    int lr = t >> 4, lc = (t & 15) * 4;
#pragma unroll
    for (int r = 0; r < 4; r++) {
        int n = n0 + lr + r * 16;
        float4 v = *(const float4*)(feat + ((size_t)b * Nn + n) * Dd + d0 + lc);
        sm[lr + r * 16][lc + 0] = v.x;
        sm[lr + r * 16][lc + 1] = v.y;
        sm[lr + r * 16][lc + 2] = v.z;
        sm[lr + r * 16][lc + 3] = v.w;
        *(uint2*)(g_fh + ((size_t)b * Nn + n) * (Dd / 2) + (d0 + lc) / 2) =
            make_uint2(pk2(v.x, v.y), pk2(v.z, v.w));
    }
    __syncthreads();
    int d = t >> 2, npb = (t & 3) * 8;
    u32 w[8];
#pragma unroll
    for (int j = 0; j < 8; j++)
        w[j] = pk2(sm[2 * (npb + j)][d], sm[2 * (npb + j) + 1][d]);
    u32* dst = g_fTh + ((size_t)b * Dd + d0 + d) * (Nn / 2) + n0 / 2 + npb;
    *(uint4*)dst = make_uint4(w[0], w[1], w[2], w[3]);
    *(uint4*)(dst + 4) = make_uint4(w[4], w[5], w[6], w[7]);
}

// W[d][e] -> g_wt[e][(d,d+1)]
__global__ void k_prepW(const float* __restrict__ W) {
    __shared__ float sm[64][65];
    int d0 = blockIdx.y * 64, e0 = blockIdx.x * 64;
    int t = threadIdx.x;
    int lr = t >> 4, lc = (t & 15) * 4;
#pragma unroll
    for (int r = 0; r < 4; r++) {
        float4 v = *(const float4*)(W + (size_t)(d0 + lr + r * 16) * Dd + e0 + lc);
        sm[lr + r * 16][lc + 0] = v.x;
        sm[lr + r * 16][lc + 1] = v.y;
        sm[lr + r * 16][lc + 2] = v.z;
        sm[lr + r * 16][lc + 3] = v.w;
    }
    __syncthreads();
    int e = t >> 2, dpb = (t & 3) * 8;
    u32 w[8];
#pragma unroll
    for (int j = 0; j < 8; j++)
        w[j] = pk2(sm[2 * (dpb + j)][e], sm[2 * (dpb + j) + 1][e]);
    u32* dst = g_wt + (size_t)(e0 + e) * (Dd / 2) + d0 / 2 + dpb;
    *(uint4*)dst = make_uint4(w[0], w[1], w[2], w[3]);
    *(uint4*)(dst + 4) = make_uint4(w[4], w[5], w[6], w[7]);
}

// ================= GEMM framework: block 128x256, warp tile 64x64 =================
// smem rows = 8 words (32B, 2x16B chunks), chunk swizzle: phys = c ^ ((row>>2)&1)
// A stage 4KB (128 rows), B stage 8KB (256 rows), double buffered.

__device__ __forceinline__ void ldA(u32 dst, const u32* src, size_t ldw, int kw, int tid) {
    int r = tid >> 1, c = tid & 1;
    cpa16(dst + (u32)(r * 32 + ((c ^ ((r >> 2) & 1)) * 16)),
          src + (size_t)r * ldw + kw + c * 4);
}
__device__ __forceinline__ void ldB(u32 dst, const u32* src, size_t ldw, int kw, int tid) {
    int r0 = tid >> 1, c = tid & 1;
#pragma unroll
    for (int i = 0; i < 2; i++) {
        int r = r0 + i * 128;
        cpa16(dst + (u32)(r * 32 + ((c ^ ((r >> 2) & 1)) * 16)),
              src + (size_t)r * ldw + kw + c * 4);
    }
}

#define GEMM_DECLS                                                          \
    __shared__ __align__(16) u32 sA[2][1024], sB[2][2048];                  \
    u32 sAu = s2u(sA), sBu = s2u(sB);                                       \
    int tid = threadIdx.x, lane = tid & 31, warp = tid >> 5;                \
    int wm = warp >> 2, wn = warp & 3;                                      \
    int lg = lane >> 2, lt = lane & 3;                                      \
    int rowA = wm * 64 + (lane & 15);                                       \
    u32 aoff = (u32)(rowA * 32 + (((lane >> 4) ^ ((rowA >> 2) & 1)) * 16)); \
    int rowB = wn * 64 + (lane & 7) + ((lane >> 4) << 3);                   \
    u32 boff = (u32)(rowB * 32 + ((((lane >> 3) & 1) ^ ((rowB >> 2) & 1)) * 16)); \
    float acc[4][8][4];                                                     \
    _Pragma("unroll") for (int i = 0; i < 4; i++)                           \
    _Pragma("unroll") for (int j = 0; j < 8; j++)                           \
    _Pragma("unroll") for (int r = 0; r < 4; r++) acc[i][j][r] = 0.f;

#define COMPUTE16(pA, pB) {                                                 \
    u32 af[4][4], bq[4][4];                                                 \
    _Pragma("unroll") for (int mt = 0; mt < 4; mt++)                        \
        ldsm4(af[mt][0], af[mt][1], af[mt][2], af[mt][3],                   \
              sAu + (pA) + aoff + mt * 512);                                \
    _Pragma("unroll") for (int pq = 0; pq < 4; pq++)                        \
        ldsm4(bq[pq][0], bq[pq][1], bq[pq][2], bq[pq][3],                   \
              sBu + (pB) + boff + pq * 512);                                \
    _Pragma("unroll") for (int mt = 0; mt < 4; mt++)                        \
        _Pragma("unroll") for (int nt = 0; nt < 8; nt++)                    \
            mma_bf16(acc[mt][nt][0], acc[mt][nt][1],                        \
                     acc[mt][nt][2], acc[mt][nt][3],                        \
                     af[mt][0], af[mt][1], af[mt][2], af[mt][3],            \
                     bq[nt >> 1][(nt & 1) * 2], bq[nt >> 1][(nt & 1) * 2 + 1]); }

#define MAINLOOP(Asrc, Aldw, Bsrc, Bldw, S)                                 \
    ldA(sAu, (Asrc), (Aldw), 0, tid); ldB(sBu, (Bsrc), (Bldw), 0, tid);     \
    CP_COMMIT;                                                              \
    ldA(sAu + 4096, (Asrc), (Aldw), 8, tid);                                \
    ldB(sBu + 8192, (Bsrc), (Bldw), 8, tid);                                \
    CP_COMMIT;                                                              \
    for (int s = 0; s < (S); s++) {                                         \
        int p = s & 1;                                                      \
        CP_WAIT1; __syncthreads();                                          \
        COMPUTE16(p * 4096, p * 8192)                                       \
        __syncthreads();                                                    \
        if (s + 2 < (S)) {                                                  \
            ldA(sAu + p * 4096, (Asrc), (Aldw), (s + 2) * 8, tid);          \
            ldB(sBu + p * 8192, (Bsrc), (Bldw), (s + 2) * 8, tid);          \
        }                                                                   \
        CP_COMMIT;                                                          \
    }

// ---------------- K2: f1 = feat @ W + b -> g_fnh (+ row |f1|^2) ----------
__global__ __launch_bounds__(256, 1)
void k_linear(const float* __restrict__ bias) {
    GEMM_DECLS
    int m0 = blockIdx.y * 128;  // over B*N
    int e0 = blockIdx.x * 256;  // over Dd
    const u32* Asrc = g_fh + (size_t)m0 * (Dd / 2);
    const u32* Bsrc = g_wt + (size_t)e0 * (Dd / 2);
    MAINLOOP(Asrc, Dd / 2, Bsrc, Dd / 2, 32)
    float rs[4][2];
#pragma unroll
    for (int mt = 0; mt < 4; mt++) { rs[mt][0] = 0.f; rs[mt][1] = 0.f; }
#pragma unroll
    for (int mt = 0; mt < 4; mt++) {
        int row = m0 + wm * 64 + mt * 16 + lg;
#pragma unroll
        for (int nt = 0; nt < 8; nt++) {
            int col = e0 + wn * 64 + nt * 8 + lt * 2;
            float b0 = __ldg(bias + col), b1 = __ldg(bias + col + 1);
            float f0 = acc[mt][nt][0] + b0, f1 = acc[mt][nt][1] + b1;
            float f2 = acc[mt][nt][2] + b0, f3 = acc[mt][nt][3] + b1;
            g_fnh[((size_t)row * Dd + col) >> 1] = pk2(f0, f1);
            g_fnh[((size_t)(row + 8) * Dd + col) >> 1] = pk2(f2, f3);
            rs[mt][0] += f0 * f0 + f1 * f1;
            rs[mt][1] += f2 * f2 + f3 * f3;
        }
    }
#pragma unroll
    for (int mt = 0; mt < 4; mt++)
#pragma unroll
        for (int r = 0; r < 2; r++) {
            float v = rs[mt][r];
            v += __shfl_xor_sync(0xffffffffu, v, 1);
            v += __shfl_xor_sync(0xffffffffu, v, 2);
            if (lt == 0)
                atomicAdd(&g_rn[m0 + wm * 64 + mt * 16 + lg + r * 8], v);
        }
}

// ---------------- K3: e^T = exp(tn @ f1^T * invnorm) -> g_eth; row sums ---
__global__ __launch_bounds__(256, 1)
void k_sim() {
    GEMM_DECLS
    __shared__ float sc[256];
    int b = blockIdx.z;
    int m0 = blockIdx.y * 128;  // over Mm
    int n0 = blockIdx.x * 256;  // over Nn
    const u32* Asrc = g_tnh + (size_t)m0 * (Dd / 2);
    const u32* Bsrc = g_fnh + ((size_t)b * Nn + n0) * (Dd / 2);
    MAINLOOP(Asrc, Dd / 2, Bsrc, Dd / 2, 32)
    sc[tid] = 1.f / fmaxf(sqrtf(g_rn[b * Nn + n0 + tid]), 1e-8f);
    __syncthreads();
    float rs[4][2];
#pragma unroll
    for (int mt = 0; mt < 4; mt++) { rs[mt][0] = 0.f; rs[mt][1] = 0.f; }
#pragma unroll
    for (int mt = 0; mt < 4; mt++) {
        int m = m0 + wm * 64 + mt * 16 + lg;
#pragma unroll
        for (int nt = 0; nt < 8; nt++) {
            int cl = wn * 64 + nt * 8 + lt * 2;  // col within block
            float i0 = sc[cl], i1 = sc[cl + 1];
            float e0 = __expf(acc[mt][nt][0] * i0);
            float e1 = __expf(acc[mt][nt][1] * i1);
            float e2 = __expf(acc[mt][nt][2] * i0);
            float e3 = __expf(acc[mt][nt][3] * i1);
            int nw = (n0 + cl) >> 1;
            g_eth[((size_t)b * Mm + m) * (Nn / 2) + nw] = pk2(e0, e1);
            g_eth[((size_t)b * Mm + m + 8) * (Nn / 2) + nw] = pk2(e2, e3);
            rs[mt][0] += e0 + e1;
            rs[mt][1] += e2 + e3;
        }
    }
#pragma unroll
    for (int mt = 0; mt < 4; mt++)
#pragma unroll
        for (int r = 0; r < 2; r++) {
            float v = rs[mt][r];
            v += __shfl_xor_sync(0xffffffffu, v, 1);
            v += __shfl_xor_sync(0xffffffffu, v, 2);
            if (lt == 0)
                atomicAdd(&g_s[b * Mm + m0 + wm * 64 + mt * 16 + lg + r * 8], v);
        }
}

// ---------------- K4: out[...,:512] = (e @ feat) / s ----------------------
__global__ __launch_bounds__(256, 1)
void k_out(float* __restrict__ out) {
    GEMM_DECLS
    int b = blockIdx.z;
    int m0 = blockIdx.y * 128;  // over Mm
    int d0 = blockIdx.x * 256;  // over Dd
    const u32* Asrc = g_eth + ((size_t)b * Mm + m0) * (Nn / 2);
    const u32* Bsrc = g_fTh + ((size_t)b * Dd + d0) * (Nn / 2);
    MAINLOOP(Asrc, Nn / 2, Bsrc, Nn / 2, Nn / 16)
#pragma unroll
    for (int mt = 0; mt < 4; mt++) {
        int row = m0 + wm * 64 + mt * 16 + lg;
        float i0 = 1.f / g_s[b * Mm + row];
        float i1 = 1.f / g_s[b * Mm + row + 8];
#pragma unroll
        for (int nt = 0; nt < 8; nt++) {
            int col = d0 + wn * 64 + nt * 8 + lt * 2;
            *(float2*)(out + ((size_t)(b * Mm + row)) * (2 * Dd) + col) =
                make_float2(acc[mt][nt][0] * i0, acc[mt][nt][1] * i0);
            *(float2*)(out + ((size_t)(b * Mm + row + 8)) * (2 * Dd) + col) =
                make_float2(acc[mt][nt][2] * i1, acc[mt][nt][3] * i1);
        }
    }
}

// ---------------- launch ----------------
extern "C" void kernel_launch(void* const* d_in, const int* in_sizes, int n_in,
                              void* d_out, int out_size) {
    const float* features = (const float*)d_in[0];
    const float* text     = (const float*)d_in[1];
    const float* W        = (const float*)d_in[2];
    const float* bias     = (const float*)d_in[3];
    float* out = (float*)d_out;

    k_zero<<<(Bb * Nn + 255) / 256, 256>>>();
    k_text<<<Mm, 128>>>(text, out);
    k_prepW<<<dim3(Dd / 64, Dd / 64), 256>>>(W);
    k_prepfeat<<<dim3(Nn / 64, Dd / 64, Bb), 256>>>(features);
    k_linear<<<dim3(Dd / 256, (Bb * Nn) / 128), 256>>>(bias);
    k_sim<<<dim3(Nn / 256, Mm / 128, Bb), 256>>>();
    k_out<<<dim3(Dd / 256, Mm / 128, Bb), 256>>>(out);
}

// round 8
// speedup vs baseline: 7.6071x; 1.1007x over previous
#include <cuda_runtime.h>
#include <cuda_bf16.h>
#include <math.h>

#define Bb 8
#define Nn 4096
#define Mm 2048
#define Dd 512
typedef unsigned u32;

// ---------------- scratch (bf16 packed words, 16B aligned) ----------------
__device__ __align__(16) u32 g_fh [(size_t)Bb * Nn * (Dd / 2)];  // feat rows bf16
__device__ __align__(16) u32 g_fTh[(size_t)Bb * Dd * (Nn / 2)];  // feat^T bf16
__device__ __align__(16) u32 g_wt [(size_t)Dd * (Dd / 2)];       // W^T rows bf16
__device__ __align__(16) u32 g_tnh[(size_t)Mm * (Dd / 2)];       // tn rows bf16
__device__ __align__(16) u32 g_fnh[(size_t)Bb * Nn * (Dd / 2)];  // f1 (unnormalized) bf16
__device__ __align__(16) u32 g_eth[(size_t)Bb * Mm * (Nn / 2)];  // e^T: [b][m][(n,n+1)]
__device__ float g_s[Bb * Mm];   // softmax denominators
__device__ float g_rn[Bb * Nn];  // per-row |f1|^2

__device__ __forceinline__ u32 pk2(float lo, float hi) {
    __nv_bfloat162 h = __floats2bfloat162_rn(lo, hi);
    return *(u32*)&h;
}
__device__ __forceinline__ u32 s2u(const void* p) {
    return (u32)__cvta_generic_to_shared(p);
}
__device__ __forceinline__ void cpa16(u32 saddr, const void* g) {
    asm volatile("cp.async.cg.shared.global [%0], [%1], 16;" :: "r"(saddr), "l"(g));
}
#define CP_COMMIT asm volatile("cp.async.commit_group;" ::: "memory")
#define CP_WAIT2 asm volatile("cp.async.wait_group 2;" ::: "memory")
__device__ __forceinline__ void ldsm4(u32& r0, u32& r1, u32& r2, u32& r3, u32 addr) {
    asm volatile("ldmatrix.sync.aligned.m8n8.x4.shared.b16 {%0,%1,%2,%3}, [%4];"
                 : "=r"(r0), "=r"(r1), "=r"(r2), "=r"(r3) : "r"(addr));
}
__device__ __forceinline__ void mma_bf16(float& d0, float& d1, float& d2, float& d3,
                                         u32 a0, u32 a1, u32 a2, u32 a3,
                                         u32 b0, u32 b1) {
    asm volatile(
        "mma.sync.aligned.m16n8k16.row.col.f32.bf16.bf16.f32 "
        "{%0,%1,%2,%3}, {%4,%5,%6,%7}, {%8,%9}, {%0,%1,%2,%3};"
        : "+f"(d0), "+f"(d1), "+f"(d2), "+f"(d3)
        : "r"(a0), "r"(a1), "r"(a2), "r"(a3), "r"(b0), "r"(b1));
}

// ---------------- small kernels ----------------
__global__ void k_zero() {
    int i = blockIdx.x * 256 + threadIdx.x;
    if (i < Bb * Mm) g_s[i] = 0.f;
    if (i < Bb * Nn) g_rn[i] = 0.f;
}

__global__ void k_text(const float* __restrict__ text, float* __restrict__ out) {
    int m = blockIdx.x, tid = threadIdx.x;
    const float4* t1 = (const float4*)(text + (size_t)Mm * Dd + (size_t)m * Dd);
    float4 v = t1[tid];
    float ss = v.x * v.x + v.y * v.y + v.z * v.z + v.w * v.w;
#pragma unroll
    for (int o = 16; o > 0; o >>= 1) ss += __shfl_xor_sync(0xffffffffu, ss, o);
    __shared__ float ws[4];
    if ((tid & 31) == 0) ws[tid >> 5] = ss;
    __syncthreads();
    float inv = 1.f / fmaxf(sqrtf(ws[0] + ws[1] + ws[2] + ws[3]), 1e-8f);
    *(uint2*)(g_tnh + (size_t)m * (Dd / 2) + tid * 2) =
        make_uint2(pk2(v.x * inv, v.y * inv), pk2(v.z * inv, v.w * inv));
#pragma unroll
    for (int b = 0; b < Bb; b++) {
        float4* o = (float4*)(out + ((size_t)(b * Mm + m)) * (2 * Dd) + Dd);
        o[tid] = v;
    }
}

// features -> g_fh (row-major bf16) + g_fTh (transpose-pack)
__global__ void k_prepfeat(const float* __restrict__ feat) {
    __shared__ float sm[64][65];
    int b = blockIdx.z, d0 = blockIdx.y * 64, n0 = blockIdx.x * 64;
    int t = threadIdx.x;
    int lr = t >> 4, lc = (t & 15) * 4;
#pragma unroll
    for (int r = 0; r < 4; r++) {
        int n = n0 + lr + r * 16;
        float4 v = *(const float4*)(feat + ((size_t)b * Nn + n) * Dd + d0 + lc);
        sm[lr + r * 16][lc + 0] = v.x;
        sm[lr + r * 16][lc + 1] = v.y;
        sm[lr + r * 16][lc + 2] = v.z;
        sm[lr + r * 16][lc + 3] = v.w;
        *(uint2*)(g_fh + ((size_t)b * Nn + n) * (Dd / 2) + (d0 + lc) / 2) =
            make_uint2(pk2(v.x, v.y), pk2(v.z, v.w));
    }
    __syncthreads();
    int d = t >> 2, npb = (t & 3) * 8;
    u32 w[8];
#pragma unroll
    for (int j = 0; j < 8; j++)
        w[j] = pk2(sm[2 * (npb + j)][d], sm[2 * (npb + j) + 1][d]);
    u32* dst = g_fTh + ((size_t)b * Dd + d0 + d) * (Nn / 2) + n0 / 2 + npb;
    *(uint4*)dst = make_uint4(w[0], w[1], w[2], w[3]);
    *(uint4*)(dst + 4) = make_uint4(w[4], w[5], w[6], w[7]);
}

// W[d][e] -> g_wt[e][(d,d+1)]
__global__ void k_prepW(const float* __restrict__ W) {
    __shared__ float sm[64][65];
    int d0 = blockIdx.y * 64, e0 = blockIdx.x * 64;
    int t = threadIdx.x;
    int lr = t >> 4, lc = (t & 15) * 4;
#pragma unroll
    for (int r = 0; r < 4; r++) {
        float4 v = *(const float4*)(W + (size_t)(d0 + lr + r * 16) * Dd + e0 + lc);
        sm[lr + r * 16][lc + 0] = v.x;
        sm[lr + r * 16][lc + 1] = v.y;
        sm[lr + r * 16][lc + 2] = v.z;
        sm[lr + r * 16][lc + 3] = v.w;
    }
    __syncthreads();
    int e = t >> 2, dpb = (t & 3) * 8;
    u32 w[8];
#pragma unroll
    for (int j = 0; j < 8; j++)
        w[j] = pk2(sm[2 * (dpb + j)][e], sm[2 * (dpb + j) + 1][e]);
    u32* dst = g_wt + (size_t)(e0 + e) * (Dd / 2) + d0 / 2 + dpb;
    *(uint4*)dst = make_uint4(w[0], w[1], w[2], w[3]);
    *(uint4*)(dst + 4) = make_uint4(w[4], w[5], w[6], w[7]);
}

// ========== GEMM framework: block 128x256, warp tile 64x64, 4-stage pipe ==========
// smem rows = 8 words (32B), chunk swizzle: phys = c ^ ((row>>2)&1)
// stage: A 4KB (128 rows) + B 8KB (256 rows); 4 stages, single sync/iter.

__device__ __forceinline__ void ldA(u32 dst, const u32* src, size_t ldw, int kw, int tid) {
    int r = tid >> 1, c = tid & 1;
    cpa16(dst + (u32)(r * 32 + ((c ^ ((r >> 2) & 1)) * 16)),
          src + (size_t)r * ldw + kw + c * 4);
}
__device__ __forceinline__ void ldB(u32 dst, const u32* src, size_t ldw, int kw, int tid) {
    int r0 = tid >> 1, c = tid & 1;
#pragma unroll
    for (int i = 0; i < 2; i++) {
        int r = r0 + i * 128;
        cpa16(dst + (u32)(r * 32 + ((c ^ ((r >> 2) & 1)) * 16)),
              src + (size_t)r * ldw + kw + c * 4);
    }
}

#define GEMM_DECLS                                                          \
    __shared__ __align__(16) u32 sA[4][1024], sB[4][2048];                  \
    u32 sAu = s2u(sA), sBu = s2u(sB);                                       \
    int tid = threadIdx.x, lane = tid & 31, warp = tid >> 5;                \
    int wm = warp >> 2, wn = warp & 3;                                      \
    int lg = lane >> 2, lt = lane & 3;                                      \
    int rowA = wm * 64 + (lane & 15);                                       \
    u32 aoff = (u32)(rowA * 32 + (((lane >> 4) ^ ((rowA >> 2) & 1)) * 16)); \
    int rowB = wn * 64 + (lane & 7) + ((lane >> 4) << 3);                   \
    u32 boff = (u32)(rowB * 32 + ((((lane >> 3) & 1) ^ ((rowB >> 2) & 1)) * 16)); \
    float acc[4][8][4];                                                     \
    _Pragma("unroll") for (int i = 0; i < 4; i++)                           \
    _Pragma("unroll") for (int j = 0; j < 8; j++)                           \
    _Pragma("unroll") for (int r = 0; r < 4; r++) acc[i][j][r] = 0.f;

#define COMPUTE16(pA, pB) {                                                 \
    u32 af[4][4], bq[4][4];                                                 \
    _Pragma("unroll") for (int mt = 0; mt < 4; mt++)                        \
        ldsm4(af[mt][0], af[mt][1], af[mt][2], af[mt][3],                   \
              sAu + (pA) + aoff + mt * 512);                                \
    _Pragma("unroll") for (int pq = 0; pq < 4; pq++)                        \
        ldsm4(bq[pq][0], bq[pq][1], bq[pq][2], bq[pq][3],                   \
              sBu + (pB) + boff + pq * 512);                                \
    _Pragma("unroll") for (int mt = 0; mt < 4; mt++)                        \
        _Pragma("unroll") for (int nt = 0; nt < 8; nt++)                    \
            mma_bf16(acc[mt][nt][0], acc[mt][nt][1],                        \
                     acc[mt][nt][2], acc[mt][nt][3],                        \
                     af[mt][0], af[mt][1], af[mt][2], af[mt][3],            \
                     bq[nt >> 1][(nt & 1) * 2], bq[nt >> 1][(nt & 1) * 2 + 1]); }

// 4-stage pipeline, single __syncthreads per iter, wait_group 2.
// Slot written at iter s ((s+3)&3) was read at iter s-1; barrier at iter-s
// entry orders all reads before the new writes (CUTLASS multistage invariant).
#define MAINLOOP(Asrc, Aldw, Bsrc, Bldw, S)                                 \
    _Pragma("unroll") for (int st = 0; st < 3; st++) {                      \
        ldA(sAu + st * 4096, (Asrc), (Aldw), st * 8, tid);                  \
        ldB(sBu + st * 8192, (Bsrc), (Bldw), st * 8, tid);                  \
        CP_COMMIT;                                                          \
    }                                                                       \
    for (int s = 0; s < (S); s++) {                                         \
        int p = s & 3;                                                      \
        CP_WAIT2; __syncthreads();                                          \
        COMPUTE16(p * 4096, p * 8192)                                       \
        int f = s + 3;                                                      \
        if (f < (S)) {                                                      \
            int q = f & 3;                                                  \
            ldA(sAu + q * 4096, (Asrc), (Aldw), f * 8, tid);                \
            ldB(sBu + q * 8192, (Bsrc), (Bldw), f * 8, tid);                \
        }                                                                   \
        CP_COMMIT;                                                          \
    }

// ---------------- K2: f1 = feat @ W + b -> g_fnh (+ row |f1|^2) ----------
__global__ __launch_bounds__(256, 1)
void k_linear(const float* __restrict__ bias) {
    GEMM_DECLS
    int m0 = blockIdx.y * 128;  // over B*N
    int e0 = blockIdx.x * 256;  // over Dd
    const u32* Asrc = g_fh + (size_t)m0 * (Dd / 2);
    const u32* Bsrc = g_wt + (size_t)e0 * (Dd / 2);
    MAINLOOP(Asrc, Dd / 2, Bsrc, Dd / 2, 32)
    float rs[4][2];
#pragma unroll
    for (int mt = 0; mt < 4; mt++) { rs[mt][0] = 0.f; rs[mt][1] = 0.f; }
#pragma unroll
    for (int mt = 0; mt < 4; mt++) {
        int row = m0 + wm * 64 + mt * 16 + lg;
#pragma unroll
        for (int nt = 0; nt < 8; nt++) {
            int col = e0 + wn * 64 + nt * 8 + lt * 2;
            float b0 = __ldg(bias + col), b1 = __ldg(bias + col + 1);
            float f0 = acc[mt][nt][0] + b0, f1 = acc[mt][nt][1] + b1;
            float f2 = acc[mt][nt][2] + b0, f3 = acc[mt][nt][3] + b1;
            g_fnh[((size_t)row * Dd + col) >> 1] = pk2(f0, f1);
            g_fnh[((size_t)(row + 8) * Dd + col) >> 1] = pk2(f2, f3);
            rs[mt][0] += f0 * f0 + f1 * f1;
            rs[mt][1] += f2 * f2 + f3 * f3;
        }
    }
#pragma unroll
    for (int mt = 0; mt < 4; mt++)
#pragma unroll
        for (int r = 0; r < 2; r++) {
            float v = rs[mt][r];
            v += __shfl_xor_sync(0xffffffffu, v, 1);
            v += __shfl_xor_sync(0xffffffffu, v, 2);
            if (lt == 0)
                atomicAdd(&g_rn[m0 + wm * 64 + mt * 16 + lg + r * 8], v);
        }
}

// ---------------- K3: e^T = exp(tn @ f1^T * invnorm) -> g_eth; row sums ---
__global__ __launch_bounds__(256, 1)
void k_sim() {
    GEMM_DECLS
    __shared__ float sc[256];
    int b = blockIdx.z;
    int m0 = blockIdx.y * 128;  // over Mm
    int n0 = blockIdx.x * 256;  // over Nn
    const u32* Asrc = g_tnh + (size_t)m0 * (Dd / 2);
    const u32* Bsrc = g_fnh + ((size_t)b * Nn + n0) * (Dd / 2);
    MAINLOOP(Asrc, Dd / 2, Bsrc, Dd / 2, 32)
    sc[tid] = 1.f / fmaxf(sqrtf(g_rn[b * Nn + n0 + tid]), 1e-8f);
    __syncthreads();
    float rs[4][2];
#pragma unroll
    for (int mt = 0; mt < 4; mt++) { rs[mt][0] = 0.f; rs[mt][1] = 0.f; }
#pragma unroll
    for (int mt = 0; mt < 4; mt++) {
        int m = m0 + wm * 64 + mt * 16 + lg;
#pragma unroll
        for (int nt = 0; nt < 8; nt++) {
            int cl = wn * 64 + nt * 8 + lt * 2;  // col within block
            float i0 = sc[cl], i1 = sc[cl + 1];
            float e0 = __expf(acc[mt][nt][0] * i0);
            float e1 = __expf(acc[mt][nt][1] * i1);
            float e2 = __expf(acc[mt][nt][2] * i0);
            float e3 = __expf(acc[mt][nt][3] * i1);
            int nw = (n0 + cl) >> 1;
            g_eth[((size_t)b * Mm + m) * (Nn / 2) + nw] = pk2(e0, e1);
            g_eth[((size_t)b * Mm + m + 8) * (Nn / 2) + nw] = pk2(e2, e3);
            rs[mt][0] += e0 + e1;
            rs[mt][1] += e2 + e3;
        }
    }
#pragma unroll
    for (int mt = 0; mt < 4; mt++)
#pragma unroll
        for (int r = 0; r < 2; r++) {
            float v = rs[mt][r];
            v += __shfl_xor_sync(0xffffffffu, v, 1);
            v += __shfl_xor_sync(0xffffffffu, v, 2);
            if (lt == 0)
                atomicAdd(&g_s[b * Mm + m0 + wm * 64 + mt * 16 + lg + r * 8], v);
        }
}

// ---------------- K4: out[...,:512] = (e @ feat) / s ----------------------
__global__ __launch_bounds__(256, 1)
void k_out(float* __restrict__ out) {
    GEMM_DECLS
    int b = blockIdx.z;
    int m0 = blockIdx.y * 128;  // over Mm
    int d0 = blockIdx.x * 256;  // over Dd
    const u32* Asrc = g_eth + ((size_t)b * Mm + m0) * (Nn / 2);
    const u32* Bsrc = g_fTh + ((size_t)b * Dd + d0) * (Nn / 2);
    MAINLOOP(Asrc, Nn / 2, Bsrc, Nn / 2, Nn / 16)
#pragma unroll
    for (int mt = 0; mt < 4; mt++) {
        int row = m0 + wm * 64 + mt * 16 + lg;
        float i0 = 1.f / g_s[b * Mm + row];
        float i1 = 1.f / g_s[b * Mm + row + 8];
#pragma unroll
        for (int nt = 0; nt < 8; nt++) {
            int col = d0 + wn * 64 + nt * 8 + lt * 2;
            *(float2*)(out + ((size_t)(b * Mm + row)) * (2 * Dd) + col) =
                make_float2(acc[mt][nt][0] * i0, acc[mt][nt][1] * i0);
            *(float2*)(out + ((size_t)(b * Mm + row + 8)) * (2 * Dd) + col) =
                make_float2(acc[mt][nt][2] * i1, acc[mt][nt][3] * i1);
        }
    }
}

// ---------------- launch ----------------
extern "C" void kernel_launch(void* const* d_in, const int* in_sizes, int n_in,
                              void* d_out, int out_size) {
    const float* features = (const float*)d_in[0];
    const float* text     = (const float*)d_in[1];
    const float* W        = (const float*)d_in[2];
    const float* bias     = (const float*)d_in[3];
    float* out = (float*)d_out;

    k_zero<<<(Bb * Nn + 255) / 256, 256>>>();
    k_text<<<Mm, 128>>>(text, out);
    k_prepW<<<dim3(Dd / 64, Dd / 64), 256>>>(W);
    k_prepfeat<<<dim3(Nn / 64, Dd / 64, Bb), 256>>>(features);
    k_linear<<<dim3(Dd / 256, (Bb * Nn) / 128), 256>>>(bias);
    k_sim<<<dim3(Nn / 256, Mm / 128, Bb), 256>>>();
    k_out<<<dim3(Dd / 256, Mm / 128, Bb), 256>>>(out);
}